// round 2
// baseline (speedup 1.0000x reference)
#include <cuda_runtime.h>
#include <cstdint>

// Problem constants
#define BB 2
#define SS 2048
#define DD 1024
#define HH 16
#define HD 64
#define NTOK (BB*SS)          // 4096
#define EPS 1e-5f

// ---------------- device scratch (allocation-free rule: device globals) ----
__device__ float g_q[(size_t)BB*HH*SS*HD];     // head-major [B,H,S,HD], pre-scaled by 1/8
__device__ float g_k[(size_t)BB*HH*SS*HD];     // head-major
__device__ float g_v[(size_t)BB*HH*SS*HD];     // head-major
__device__ float g_attn[(size_t)NTOK*DD];      // token-major [B*S, D]
__device__ float g_proj[(size_t)NTOK*DD];      // token-major

// ---------------------------------------------------------------------------
// Tiled SGEMM: C[M=4096, N=1024] = A[4096,1024] @ W[1024,1024] + bias, * scale
// head_major=1 -> write to [B,H,S,HD] layout; else token-major [M, N].
// BM=BN=128, BK=8, 256 threads, 8x8 per thread.
// ---------------------------------------------------------------------------
__global__ void __launch_bounds__(256) gemm_kernel(
    const float* __restrict__ A, const float* __restrict__ W,
    const float* __restrict__ bias, float* __restrict__ C,
    float scale, int head_major)
{
    __shared__ float As[8][128];
    __shared__ float Bs[8][128];

    const int tid  = threadIdx.x;
    const int brow = blockIdx.y * 128;
    const int bcol = blockIdx.x * 128;

    const int arow   = tid >> 1;          // 0..127
    const int acol   = (tid & 1) * 4;     // 0 or 4
    const int brow_l = tid >> 5;          // 0..7
    const int bcol_l = (tid & 31) * 4;    // 0..124

    const int tx = tid & 15;
    const int ty = tid >> 4;

    float acc[8][8];
#pragma unroll
    for (int i = 0; i < 8; i++)
#pragma unroll
        for (int j = 0; j < 8; j++) acc[i][j] = 0.f;

    const float* Aptr = A + (size_t)(brow + arow) * 1024 + acol;
    const float* Bptr = W + (size_t)brow_l * 1024 + bcol + bcol_l;

    float4 av = *(const float4*)(Aptr);
    float4 bv = *(const float4*)(Bptr);

    for (int k0 = 0; k0 < 1024; k0 += 8) {
        As[acol + 0][arow] = av.x;
        As[acol + 1][arow] = av.y;
        As[acol + 2][arow] = av.z;
        As[acol + 3][arow] = av.w;
        *(float4*)&Bs[brow_l][bcol_l] = bv;
        __syncthreads();

        if (k0 + 8 < 1024) {
            Aptr += 8;
            Bptr += (size_t)8 * 1024;
            av = *(const float4*)(Aptr);
            bv = *(const float4*)(Bptr);
        }

#pragma unroll
        for (int kk = 0; kk < 8; kk++) {
            float a[8], b[8];
            *(float4*)&a[0] = *(const float4*)&As[kk][ty * 8];
            *(float4*)&a[4] = *(const float4*)&As[kk][ty * 8 + 4];
            *(float4*)&b[0] = *(const float4*)&Bs[kk][tx * 8];
            *(float4*)&b[4] = *(const float4*)&Bs[kk][tx * 8 + 4];
#pragma unroll
            for (int i = 0; i < 8; i++)
#pragma unroll
                for (int j = 0; j < 8; j++)
                    acc[i][j] = fmaf(a[i], b[j], acc[i][j]);
        }
        __syncthreads();
    }

    // epilogue
#pragma unroll
    for (int i = 0; i < 8; i++) {
        const int row  = brow + ty * 8 + i;
        const int bidx = row >> 11;        // batch
        const int srow = row & 2047;       // seq pos
#pragma unroll
        for (int j = 0; j < 8; j += 4) {
            const int col = bcol + tx * 8 + j;
            float4 b4 = *(const float4*)&bias[col];
            float4 o;
            o.x = (acc[i][j + 0] + b4.x) * scale;
            o.y = (acc[i][j + 1] + b4.y) * scale;
            o.z = (acc[i][j + 2] + b4.z) * scale;
            o.w = (acc[i][j + 3] + b4.w) * scale;
            if (head_major) {
                const int h  = col >> 6;
                const int hd = col & 63;
                float* dst = C + ((((size_t)bidx * HH + h) * SS + srow) * HD + hd);
                *(float4*)dst = o;
            } else {
                *(float4*)&C[(size_t)row * 1024 + col] = o;
            }
        }
    }
}

// ---------------------------------------------------------------------------
// Flash attention: one block per (bh, 64-row q tile). 256 threads.
// thread t -> row r = t/4 (0..63), quarter qd = t%4 (16 of 64 cols).
// Q pre-scaled; online softmax with 4-lane shuffle reductions.
// smem (dynamic): sQ/sK/sV/sP each 64 x 68 floats.
// ---------------------------------------------------------------------------
#define TPAD 68

__global__ void __launch_bounds__(256) attn_kernel()
{
    extern __shared__ float sm[];
    float* sQ = sm;
    float* sK = sm + 64 * TPAD;
    float* sV = sm + 2 * 64 * TPAD;
    float* sP = sm + 3 * 64 * TPAD;

    const int bh = blockIdx.y;
    const int qt = blockIdx.x;
    const int t  = threadIdx.x;
    const int r  = t >> 2;
    const int qd = t & 3;

    const float* qb = g_q + ((size_t)bh * SS + qt * 64) * HD;
    for (int i = t; i < 64 * 64; i += 256)
        sQ[(i >> 6) * TPAD + (i & 63)] = qb[i];

    float acc[16];
#pragma unroll
    for (int i = 0; i < 16; i++) acc[i] = 0.f;
    float mrun = -1e30f, lrun = 0.f;

    const float* kb = g_k + (size_t)bh * SS * HD;
    const float* vb = g_v + (size_t)bh * SS * HD;

    for (int kt0 = 0; kt0 < SS; kt0 += 64) {
        __syncthreads();   // protect sK/sV reuse vs previous iteration reads
        for (int i = t; i < 64 * 64; i += 256) {
            const int rr = i >> 6, dd = i & 63;
            sK[rr * TPAD + dd] = kb[(size_t)kt0 * HD + i];
            sV[rr * TPAD + dd] = vb[(size_t)kt0 * HD + i];
        }
        __syncthreads();

        // ---- scores: 16 cols (qd*16 .. +15), dot over 64 dims ----
        float s[16];
#pragma unroll
        for (int ccg = 0; ccg < 4; ccg++) {
            const int c0 = qd * 16 + ccg * 4;
            float s0 = 0.f, s1 = 0.f, s2 = 0.f, s3 = 0.f;
#pragma unroll
            for (int d4 = 0; d4 < 64; d4 += 4) {
                float4 qv = *(const float4*)&sQ[r * TPAD + d4];
                float4 k0 = *(const float4*)&sK[(c0 + 0) * TPAD + d4];
                float4 k1 = *(const float4*)&sK[(c0 + 1) * TPAD + d4];
                float4 k2 = *(const float4*)&sK[(c0 + 2) * TPAD + d4];
                float4 k3 = *(const float4*)&sK[(c0 + 3) * TPAD + d4];
                s0 = fmaf(qv.x, k0.x, fmaf(qv.y, k0.y, fmaf(qv.z, k0.z, fmaf(qv.w, k0.w, s0))));
                s1 = fmaf(qv.x, k1.x, fmaf(qv.y, k1.y, fmaf(qv.z, k1.z, fmaf(qv.w, k1.w, s1))));
                s2 = fmaf(qv.x, k2.x, fmaf(qv.y, k2.y, fmaf(qv.z, k2.z, fmaf(qv.w, k2.w, s2))));
                s3 = fmaf(qv.x, k3.x, fmaf(qv.y, k3.y, fmaf(qv.z, k3.z, fmaf(qv.w, k3.w, s3))));
            }
            s[ccg * 4 + 0] = s0; s[ccg * 4 + 1] = s1;
            s[ccg * 4 + 2] = s2; s[ccg * 4 + 3] = s3;
        }

        // ---- online softmax (4 lanes share a row; lanes r*4+qd are adjacent) ----
        float tm = s[0];
#pragma unroll
        for (int i = 1; i < 16; i++) tm = fmaxf(tm, s[i]);
        tm = fmaxf(tm, __shfl_xor_sync(0xffffffffu, tm, 1));
        tm = fmaxf(tm, __shfl_xor_sync(0xffffffffu, tm, 2));

        const float mnew  = fmaxf(mrun, tm);
        const float alpha = __expf(mrun - mnew);
        float ps = 0.f;
#pragma unroll
        for (int i = 0; i < 16; i++) {
            const float p = __expf(s[i] - mnew);
            sP[r * TPAD + qd * 16 + i] = p;
            ps += p;
        }
        ps += __shfl_xor_sync(0xffffffffu, ps, 1);
        ps += __shfl_xor_sync(0xffffffffu, ps, 2);
        lrun = lrun * alpha + ps;
        mrun = mnew;
#pragma unroll
        for (int i = 0; i < 16; i++) acc[i] *= alpha;
        __syncwarp();   // sP row written & read within the same warp

        // ---- accumulate O[r][qd*16 .. +15] over the 64 keys of this tile ----
#pragma unroll 8
        for (int c = 0; c < 64; c++) {
            const float p = sP[r * TPAD + c];
            float4 v0 = *(const float4*)&sV[c * TPAD + qd * 16 + 0];
            float4 v1 = *(const float4*)&sV[c * TPAD + qd * 16 + 4];
            float4 v2 = *(const float4*)&sV[c * TPAD + qd * 16 + 8];
            float4 v3 = *(const float4*)&sV[c * TPAD + qd * 16 + 12];
            acc[0]  = fmaf(p, v0.x, acc[0]);   acc[1]  = fmaf(p, v0.y, acc[1]);
            acc[2]  = fmaf(p, v0.z, acc[2]);   acc[3]  = fmaf(p, v0.w, acc[3]);
            acc[4]  = fmaf(p, v1.x, acc[4]);   acc[5]  = fmaf(p, v1.y, acc[5]);
            acc[6]  = fmaf(p, v1.z, acc[6]);   acc[7]  = fmaf(p, v1.w, acc[7]);
            acc[8]  = fmaf(p, v2.x, acc[8]);   acc[9]  = fmaf(p, v2.y, acc[9]);
            acc[10] = fmaf(p, v2.z, acc[10]);  acc[11] = fmaf(p, v2.w, acc[11]);
            acc[12] = fmaf(p, v3.x, acc[12]);  acc[13] = fmaf(p, v3.y, acc[13]);
            acc[14] = fmaf(p, v3.z, acc[14]);  acc[15] = fmaf(p, v3.w, acc[15]);
        }
    }

    // ---- write out (token-major, merge heads) ----
    const float inv = 1.f / lrun;
    const int b = bh >> 4, h = bh & 15;
    const int srow = qt * 64 + r;
    float* op = g_attn + ((size_t)(b * SS + srow)) * DD + h * HD + qd * 16;
#pragma unroll
    for (int g = 0; g < 4; g++) {
        float4 o;
        o.x = acc[g * 4 + 0] * inv;
        o.y = acc[g * 4 + 1] * inv;
        o.z = acc[g * 4 + 2] * inv;
        o.w = acc[g * 4 + 3] * inv;
        *(float4*)(op + g * 4) = o;
    }
}

// ---------------------------------------------------------------------------
// Residual + LayerNorm: 1 block per token row. 256 threads x 4 floats.
// ---------------------------------------------------------------------------
__global__ void __launch_bounds__(256) ln_kernel(
    const float* __restrict__ x, const float* __restrict__ gamma,
    const float* __restrict__ beta, float* __restrict__ out)
{
    __shared__ float ssum[8], ssq[8];
    const int row = blockIdx.x;
    const int t = threadIdx.x;

    float4 xv = ((const float4*)(x      + (size_t)row * DD))[t];
    float4 pv = ((const float4*)(g_proj + (size_t)row * DD))[t];
    float4 y;
    y.x = xv.x + pv.x; y.y = xv.y + pv.y; y.z = xv.z + pv.z; y.w = xv.w + pv.w;

    float s  = y.x + y.y + y.z + y.w;
    float sq = y.x * y.x + y.y * y.y + y.z * y.z + y.w * y.w;
#pragma unroll
    for (int off = 16; off > 0; off >>= 1) {
        s  += __shfl_xor_sync(0xffffffffu, s,  off);
        sq += __shfl_xor_sync(0xffffffffu, sq, off);
    }
    const int warp = t >> 5;
    if ((t & 31) == 0) { ssum[warp] = s; ssq[warp] = sq; }
    __syncthreads();
    float tot = 0.f, totq = 0.f;
#pragma unroll
    for (int i = 0; i < 8; i++) { tot += ssum[i]; totq += ssq[i]; }

    const float mu   = tot * (1.f / DD);
    const float var  = totq * (1.f / DD) - mu * mu;
    const float rstd = rsqrtf(var + EPS);

    float4 g = ((const float4*)gamma)[t];
    float4 b = ((const float4*)beta)[t];
    float4 o;
    o.x = (y.x - mu) * rstd * g.x + b.x;
    o.y = (y.y - mu) * rstd * g.y + b.y;
    o.z = (y.z - mu) * rstd * g.z + b.z;
    o.w = (y.w - mu) * rstd * g.w + b.w;
    ((float4*)(out + (size_t)row * DD))[t] = o;
}

// ---------------------------------------------------------------------------
extern "C" void kernel_launch(void* const* d_in, const int* in_sizes, int n_in,
                              void* d_out, int out_size)
{
    const float* x     = (const float*)d_in[0];
    const float* Wq    = (const float*)d_in[1];
    const float* bq    = (const float*)d_in[2];
    const float* Wk    = (const float*)d_in[3];
    const float* bk    = (const float*)d_in[4];
    const float* Wv    = (const float*)d_in[5];
    const float* bv    = (const float*)d_in[6];
    const float* Wp    = (const float*)d_in[7];
    const float* bp    = (const float*)d_in[8];
    const float* gamma = (const float*)d_in[9];
    const float* beta  = (const float*)d_in[10];
    float* out = (float*)d_out;

    float *q_ptr, *k_ptr, *v_ptr, *attn_ptr, *proj_ptr;
    cudaGetSymbolAddress((void**)&q_ptr,    g_q);
    cudaGetSymbolAddress((void**)&k_ptr,    g_k);
    cudaGetSymbolAddress((void**)&v_ptr,    g_v);
    cudaGetSymbolAddress((void**)&attn_ptr, g_attn);
    cudaGetSymbolAddress((void**)&proj_ptr, g_proj);

    dim3 gb(DD / 128, NTOK / 128);   // (8, 32)

    // QKV projections into head-major layout; Q pre-scaled by 1/sqrt(HD)=0.125
    gemm_kernel<<<gb, 256>>>(x, Wq, bq, q_ptr, 0.125f, 1);
    gemm_kernel<<<gb, 256>>>(x, Wk, bk, k_ptr, 1.0f, 1);
    gemm_kernel<<<gb, 256>>>(x, Wv, bv, v_ptr, 1.0f, 1);

    // Attention
    static bool attr_set = false;
    const size_t smem = 4 * 64 * TPAD * sizeof(float);   // ~68 KB
    if (!attr_set) {
        cudaFuncSetAttribute(attn_kernel,
                             cudaFuncAttributeMaxDynamicSharedMemorySize, (int)smem);
        attr_set = true;
    }
    dim3 ga(SS / 64, BB * HH);        // (32, 32)
    attn_kernel<<<ga, 256, smem>>>();

    // Output projection (token-major)
    gemm_kernel<<<gb, 256>>>(attn_ptr, Wp, bp, proj_ptr, 1.0f, 0);

    // Residual + LayerNorm
    ln_kernel<<<NTOK, 256>>>(x, gamma, beta, out);
}

// round 4
// speedup vs baseline: 3.9204x; 3.9204x over previous
#include <cuda_runtime.h>
#include <cstdint>

// Problem constants
#define BB 2
#define SS 2048
#define DD 1024
#define HH 16
#define HD 64
#define NTOK (BB*SS)          // 4096
#define EPS 1e-5f

typedef unsigned long long ull;

// ---------------- f32x2 packed-math helpers (SASS FFMA2 path) --------------
__device__ __forceinline__ ull pk2(float x, float y) {
    ull r; asm("mov.b64 %0, {%1, %2};" : "=l"(r) : "f"(x), "f"(y)); return r;
}
__device__ __forceinline__ ull ffma2(ull a, ull b, ull c) {
    ull d; asm("fma.rn.f32x2 %0, %1, %2, %3;" : "=l"(d) : "l"(a), "l"(b), "l"(c)); return d;
}
__device__ __forceinline__ ull fmul2(ull a, ull b) {
    ull d; asm("mul.rn.f32x2 %0, %1, %2;" : "=l"(d) : "l"(a), "l"(b)); return d;
}
__device__ __forceinline__ float2 up2(ull v) {
    float2 f; asm("mov.b64 {%0, %1}, %2;" : "=f"(f.x), "=f"(f.y) : "l"(v)); return f;
}

// ---------------- device scratch (allocation-free rule: device globals) ----
__device__ float g_q[(size_t)BB*HH*SS*HD];     // head-major [B,H,S,HD], pre-scaled by 1/8
__device__ float g_k[(size_t)BB*HH*SS*HD];     // head-major
__device__ float g_v[(size_t)BB*HH*SS*HD];     // head-major
__device__ float g_attn[(size_t)NTOK*DD];      // token-major [B*S, D]
__device__ float g_proj[(size_t)NTOK*DD];      // token-major

// ---------------------------------------------------------------------------
// Tiled SGEMM with FFMA2: C[4096,1024] = A @ W + bias (*scale)
// BM=BN=128, BK=8, 256 threads, 8 rows x 8 cols per thread.
// Thread cols = {4tx..4tx+3} U {64+4tx..}; pairs along cols (natural from
// 16B smem loads), A value duplicated into both lanes via mov.b64.
// ---------------------------------------------------------------------------
__global__ void __launch_bounds__(256, 2) gemm_kernel(
    const float* __restrict__ A, const float* __restrict__ W,
    const float* __restrict__ bias, float* __restrict__ C,
    float scale, int head_major)
{
    __shared__ float As[8][128];
    __shared__ float Bs[8][128];

    const int tid  = threadIdx.x;
    const int brow = blockIdx.y * 128;
    const int bcol = blockIdx.x * 128;

    const int arow   = tid >> 1;          // 0..127
    const int acol   = (tid & 1) * 4;     // 0 or 4
    const int brow_l = tid >> 5;          // 0..7
    const int bcol_l = (tid & 31) * 4;    // 0..124

    const int tx = tid & 15;
    const int ty = tid >> 4;

    ull acc[8][4];
#pragma unroll
    for (int i = 0; i < 8; i++)
#pragma unroll
        for (int j = 0; j < 4; j++) acc[i][j] = 0ULL;

    const float* Aptr = A + (size_t)(brow + arow) * 1024 + acol;
    const float* Bptr = W + (size_t)brow_l * 1024 + bcol + bcol_l;

    float4 av = *(const float4*)(Aptr);
    float4 bv = *(const float4*)(Bptr);

    for (int k0 = 0; k0 < 1024; k0 += 8) {
        As[acol + 0][arow] = av.x;
        As[acol + 1][arow] = av.y;
        As[acol + 2][arow] = av.z;
        As[acol + 3][arow] = av.w;
        *(float4*)&Bs[brow_l][bcol_l] = bv;
        __syncthreads();

        if (k0 + 8 < 1024) {
            Aptr += 8;
            Bptr += (size_t)8 * 1024;
            av = *(const float4*)(Aptr);
            bv = *(const float4*)(Bptr);
        }

#pragma unroll
        for (int kk = 0; kk < 8; kk++) {
            float a[8];
            *(float4*)&a[0] = *(const float4*)&As[kk][ty * 8];
            *(float4*)&a[4] = *(const float4*)&As[kk][ty * 8 + 4];
            ulonglong2 b0 = *(const ulonglong2*)&Bs[kk][tx * 4];       // cols 4tx..+3
            ulonglong2 b1 = *(const ulonglong2*)&Bs[kk][64 + tx * 4];  // cols 64+4tx..
#pragma unroll
            for (int i = 0; i < 8; i++) {
                ull ad = pk2(a[i], a[i]);
                acc[i][0] = ffma2(ad, b0.x, acc[i][0]);
                acc[i][1] = ffma2(ad, b0.y, acc[i][1]);
                acc[i][2] = ffma2(ad, b1.x, acc[i][2]);
                acc[i][3] = ffma2(ad, b1.y, acc[i][3]);
            }
        }
        __syncthreads();
    }

    // epilogue
    const int col0 = bcol + tx * 4;
    const int col1 = col0 + 64;
    float4 bb0 = *(const float4*)&bias[col0];
    float4 bb1 = *(const float4*)&bias[col1];

#pragma unroll
    for (int i = 0; i < 8; i++) {
        const int row  = brow + ty * 8 + i;
        const int bidx = row >> 11;
        const int srow = row & 2047;
        float2 p0 = up2(acc[i][0]), p1 = up2(acc[i][1]);
        float2 p2 = up2(acc[i][2]), p3 = up2(acc[i][3]);
        float4 o0, o1;
        o0.x = (p0.x + bb0.x) * scale; o0.y = (p0.y + bb0.y) * scale;
        o0.z = (p1.x + bb0.z) * scale; o0.w = (p1.y + bb0.w) * scale;
        o1.x = (p2.x + bb1.x) * scale; o1.y = (p2.y + bb1.y) * scale;
        o1.z = (p3.x + bb1.z) * scale; o1.w = (p3.y + bb1.w) * scale;
        if (head_major) {
            const int h0 = col0 >> 6, hd0 = col0 & 63;
            const int h1 = col1 >> 6, hd1 = col1 & 63;
            *(float4*)(C + ((((size_t)bidx * HH + h0) * SS + srow) * HD + hd0)) = o0;
            *(float4*)(C + ((((size_t)bidx * HH + h1) * SS + srow) * HD + hd1)) = o1;
        } else {
            *(float4*)&C[(size_t)row * 1024 + col0] = o0;
            *(float4*)&C[(size_t)row * 1024 + col1] = o1;
        }
    }
}

// ---------------------------------------------------------------------------
// Flash attention v2: one block per (bh, 128-row q tile), key tile = 128.
// 256 threads: tx = t&15, ty = t>>4.
// Scores: thread computes rows ty*8..+7 x keys {tx+16j}, pairs along row-pairs
//         (Q natural pairs from d-major sQT, K scalar duplicated).
// PV:     thread computes rows ty*8..+7 x dcols tx*4..+3, pairs along rows
//         (P natural pairs from key-major sPT, V duplicated).
// All hot smem loads broadcast or contiguous -> conflict-free.
// ---------------------------------------------------------------------------
#define PADQ 132
#define PADV 68

__global__ void __launch_bounds__(256, 1) attn_kernel()
{
    extern __shared__ float sm[];
    float* sQT = sm;                         // [64][PADQ]  d-major, cols = q-row
    float* sKT = sm + 64 * PADQ;             // [64][PADQ]  d-major, cols = key
    float* sV  = sm + 2 * 64 * PADQ;         // [128][PADV] key-major
    float* sPT = sm + 2 * 64 * PADQ + 128 * PADV;  // [128][PADQ] key-major, cols = q-row

    const int bh = blockIdx.y;
    const int qt = blockIdx.x;
    const int t  = threadIdx.x;
    const int tx = t & 15;
    const int ty = t >> 4;

    // ---- load Q transposed: sQT[d][row] ----
    const float* qb = g_q + ((size_t)bh * SS + qt * 128) * HD;
    for (int i = t; i < 2048; i += 256) {
        const int d4  = (i >> 7) << 2;   // 0..60
        const int row = i & 127;
        float4 v = *(const float4*)&qb[row * HD + d4];
        sQT[(d4 + 0) * PADQ + row] = v.x;
        sQT[(d4 + 1) * PADQ + row] = v.y;
        sQT[(d4 + 2) * PADQ + row] = v.z;
        sQT[(d4 + 3) * PADQ + row] = v.w;
    }

    ull accpv[4][4];
#pragma unroll
    for (int i = 0; i < 4; i++)
#pragma unroll
        for (int j = 0; j < 4; j++) accpv[i][j] = 0ULL;

    float m[8], l[8];
#pragma unroll
    for (int r = 0; r < 8; r++) { m[r] = -1e30f; l[r] = 0.f; }

    const float* kb = g_k + (size_t)bh * SS * HD;
    const float* vb = g_v + (size_t)bh * SS * HD;

    for (int kt0 = 0; kt0 < SS; kt0 += 128) {
        __syncthreads();   // prev PV done with sV/sPT
        // K transposed: sKT[d][key]
        for (int i = t; i < 2048; i += 256) {
            const int d4 = (i >> 7) << 2;
            const int c  = i & 127;
            float4 v = *(const float4*)&kb[(size_t)(kt0 + c) * HD + d4];
            sKT[(d4 + 0) * PADQ + c] = v.x;
            sKT[(d4 + 1) * PADQ + c] = v.y;
            sKT[(d4 + 2) * PADQ + c] = v.z;
            sKT[(d4 + 3) * PADQ + c] = v.w;
        }
        // V: sV[key][d]
        for (int i = t; i < 2048; i += 256) {
            const int c  = i >> 4;
            const int d4 = (i & 15) << 2;
            *(float4*)&sV[c * PADV + d4] = *(const float4*)&vb[(size_t)(kt0 + c) * HD + d4];
        }
        __syncthreads();

        // ---- scores: acc[rp][j] = rowpair(ty*8+2rp) x key(tx+16j) ----
        ull acc[4][8];
#pragma unroll
        for (int i = 0; i < 4; i++)
#pragma unroll
            for (int j = 0; j < 8; j++) acc[i][j] = 0ULL;

#pragma unroll 4
        for (int d = 0; d < 64; d++) {
            const float* qrow = &sQT[d * PADQ + ty * 8];
            ull qp0 = *(const ull*)&qrow[0];
            ull qp1 = *(const ull*)&qrow[2];
            ull qp2 = *(const ull*)&qrow[4];
            ull qp3 = *(const ull*)&qrow[6];
            const float* krow = &sKT[d * PADQ + tx];
#pragma unroll
            for (int j = 0; j < 8; j++) {
                const float kvj = krow[16 * j];
                ull kd = pk2(kvj, kvj);
                acc[0][j] = ffma2(qp0, kd, acc[0][j]);
                acc[1][j] = ffma2(qp1, kd, acc[1][j]);
                acc[2][j] = ffma2(qp2, kd, acc[2][j]);
                acc[3][j] = ffma2(qp3, kd, acc[3][j]);
            }
        }

        // unpack scores
        float sc[8][8];
#pragma unroll
        for (int rp = 0; rp < 4; rp++)
#pragma unroll
            for (int j = 0; j < 8; j++) {
                float2 f = up2(acc[rp][j]);
                sc[2 * rp + 0][j] = f.x;
                sc[2 * rp + 1][j] = f.y;
            }

        // ---- online softmax per row (keys distributed over 16 tx lanes) ----
        float alpha[8];
#pragma unroll
        for (int r = 0; r < 8; r++) {
            float tm = sc[r][0];
#pragma unroll
            for (int j = 1; j < 8; j++) tm = fmaxf(tm, sc[r][j]);
            tm = fmaxf(tm, __shfl_xor_sync(0xffffffffu, tm, 1));
            tm = fmaxf(tm, __shfl_xor_sync(0xffffffffu, tm, 2));
            tm = fmaxf(tm, __shfl_xor_sync(0xffffffffu, tm, 4));
            tm = fmaxf(tm, __shfl_xor_sync(0xffffffffu, tm, 8));
            const float mn = fmaxf(m[r], tm);
            alpha[r] = __expf(m[r] - mn);
            m[r] = mn;
            float ps = 0.f;
#pragma unroll
            for (int j = 0; j < 8; j++) {
                sc[r][j] = __expf(sc[r][j] - mn);
                ps += sc[r][j];
            }
            ps += __shfl_xor_sync(0xffffffffu, ps, 1);
            ps += __shfl_xor_sync(0xffffffffu, ps, 2);
            ps += __shfl_xor_sync(0xffffffffu, ps, 4);
            ps += __shfl_xor_sync(0xffffffffu, ps, 8);
            l[r] = l[r] * alpha[r] + ps;
        }

        // rescale running PV accumulators
#pragma unroll
        for (int rp = 0; rp < 4; rp++) {
            ull ap = pk2(alpha[2 * rp], alpha[2 * rp + 1]);
#pragma unroll
            for (int dc = 0; dc < 4; dc++)
                accpv[rp][dc] = fmul2(accpv[rp][dc], ap);
        }

        // store P key-major: sPT[key][row]
#pragma unroll
        for (int j = 0; j < 8; j++) {
            const int key = tx + 16 * j;
            float4 v0 = make_float4(sc[0][j], sc[1][j], sc[2][j], sc[3][j]);
            float4 v1 = make_float4(sc[4][j], sc[5][j], sc[6][j], sc[7][j]);
            *(float4*)&sPT[key * PADQ + ty * 8]     = v0;
            *(float4*)&sPT[key * PADQ + ty * 8 + 4] = v1;
        }
        __syncthreads();

        // ---- PV: accpv[rp][dc] += P[rowpair][c] * V[c][dcol] ----
#pragma unroll 4
        for (int c = 0; c < 128; c++) {
            const float* prow = &sPT[c * PADQ + ty * 8];
            ull pp0 = *(const ull*)&prow[0];
            ull pp1 = *(const ull*)&prow[2];
            ull pp2 = *(const ull*)&prow[4];
            ull pp3 = *(const ull*)&prow[6];
            float4 vv = *(const float4*)&sV[c * PADV + tx * 4];
            ull v0 = pk2(vv.x, vv.x);
            ull v1 = pk2(vv.y, vv.y);
            ull v2 = pk2(vv.z, vv.z);
            ull v3 = pk2(vv.w, vv.w);
            accpv[0][0] = ffma2(pp0, v0, accpv[0][0]);
            accpv[0][1] = ffma2(pp0, v1, accpv[0][1]);
            accpv[0][2] = ffma2(pp0, v2, accpv[0][2]);
            accpv[0][3] = ffma2(pp0, v3, accpv[0][3]);
            accpv[1][0] = ffma2(pp1, v0, accpv[1][0]);
            accpv[1][1] = ffma2(pp1, v1, accpv[1][1]);
            accpv[1][2] = ffma2(pp1, v2, accpv[1][2]);
            accpv[1][3] = ffma2(pp1, v3, accpv[1][3]);
            accpv[2][0] = ffma2(pp2, v0, accpv[2][0]);
            accpv[2][1] = ffma2(pp2, v1, accpv[2][1]);
            accpv[2][2] = ffma2(pp2, v2, accpv[2][2]);
            accpv[2][3] = ffma2(pp2, v3, accpv[2][3]);
            accpv[3][0] = ffma2(pp3, v0, accpv[3][0]);
            accpv[3][1] = ffma2(pp3, v1, accpv[3][1]);
            accpv[3][2] = ffma2(pp3, v2, accpv[3][2]);
            accpv[3][3] = ffma2(pp3, v3, accpv[3][3]);
        }
    }

    // ---- normalize + write out (token-major, merge heads) ----
    const int b = bh >> 4, h = bh & 15;
#pragma unroll
    for (int rp = 0; rp < 4; rp++) {
        const float invE = 1.f / l[2 * rp];
        const float invO = 1.f / l[2 * rp + 1];
        float2 o0 = up2(accpv[rp][0]);
        float2 o1 = up2(accpv[rp][1]);
        float2 o2 = up2(accpv[rp][2]);
        float2 o3 = up2(accpv[rp][3]);
        float4 oe = make_float4(o0.x * invE, o1.x * invE, o2.x * invE, o3.x * invE);
        float4 oo = make_float4(o0.y * invO, o1.y * invO, o2.y * invO, o3.y * invO);
        const int r0 = qt * 128 + ty * 8 + 2 * rp;
        float* p0 = g_attn + (size_t)(b * SS + r0) * DD + h * HD + tx * 4;
        *(float4*)p0        = oe;
        *(float4*)(p0 + DD) = oo;
    }
}

// ---------------------------------------------------------------------------
// Residual + LayerNorm: 1 block per token row. 256 threads x 4 floats.
// ---------------------------------------------------------------------------
__global__ void __launch_bounds__(256) ln_kernel(
    const float* __restrict__ x, const float* __restrict__ gamma,
    const float* __restrict__ beta, float* __restrict__ out)
{
    __shared__ float ssum[8], ssq[8];
    const int row = blockIdx.x;
    const int t = threadIdx.x;

    float4 xv = ((const float4*)(x      + (size_t)row * DD))[t];
    float4 pv = ((const float4*)(g_proj + (size_t)row * DD))[t];
    float4 y;
    y.x = xv.x + pv.x; y.y = xv.y + pv.y; y.z = xv.z + pv.z; y.w = xv.w + pv.w;

    float s  = y.x + y.y + y.z + y.w;
    float sq = y.x * y.x + y.y * y.y + y.z * y.z + y.w * y.w;
#pragma unroll
    for (int off = 16; off > 0; off >>= 1) {
        s  += __shfl_xor_sync(0xffffffffu, s,  off);
        sq += __shfl_xor_sync(0xffffffffu, sq, off);
    }
    const int warp = t >> 5;
    if ((t & 31) == 0) { ssum[warp] = s; ssq[warp] = sq; }
    __syncthreads();
    float tot = 0.f, totq = 0.f;
#pragma unroll
    for (int i = 0; i < 8; i++) { tot += ssum[i]; totq += ssq[i]; }

    const float mu   = tot * (1.f / DD);
    const float var  = totq * (1.f / DD) - mu * mu;
    const float rstd = rsqrtf(var + EPS);

    float4 g = ((const float4*)gamma)[t];
    float4 b = ((const float4*)beta)[t];
    float4 o;
    o.x = (y.x - mu) * rstd * g.x + b.x;
    o.y = (y.y - mu) * rstd * g.y + b.y;
    o.z = (y.z - mu) * rstd * g.z + b.z;
    o.w = (y.w - mu) * rstd * g.w + b.w;
    ((float4*)(out + (size_t)row * DD))[t] = o;
}

// ---------------------------------------------------------------------------
extern "C" void kernel_launch(void* const* d_in, const int* in_sizes, int n_in,
                              void* d_out, int out_size)
{
    const float* x     = (const float*)d_in[0];
    const float* Wq    = (const float*)d_in[1];
    const float* bq    = (const float*)d_in[2];
    const float* Wk    = (const float*)d_in[3];
    const float* bk    = (const float*)d_in[4];
    const float* Wv    = (const float*)d_in[5];
    const float* bv    = (const float*)d_in[6];
    const float* Wp    = (const float*)d_in[7];
    const float* bp    = (const float*)d_in[8];
    const float* gamma = (const float*)d_in[9];
    const float* beta  = (const float*)d_in[10];
    float* out = (float*)d_out;

    float *q_ptr, *k_ptr, *v_ptr, *attn_ptr, *proj_ptr;
    cudaGetSymbolAddress((void**)&q_ptr,    g_q);
    cudaGetSymbolAddress((void**)&k_ptr,    g_k);
    cudaGetSymbolAddress((void**)&v_ptr,    g_v);
    cudaGetSymbolAddress((void**)&attn_ptr, g_attn);
    cudaGetSymbolAddress((void**)&proj_ptr, g_proj);

    dim3 gb(DD / 128, NTOK / 128);   // (8, 32)

    // QKV projections into head-major layout; Q pre-scaled by 1/sqrt(HD)=0.125
    gemm_kernel<<<gb, 256>>>(x, Wq, bq, q_ptr, 0.125f, 1);
    gemm_kernel<<<gb, 256>>>(x, Wk, bk, k_ptr, 1.0f, 1);
    gemm_kernel<<<gb, 256>>>(x, Wv, bv, v_ptr, 1.0f, 1);

    // Attention: smem = sQT + sKT + sV + sPT
    static bool attr_set = false;
    const size_t smem = (size_t)(2 * 64 * PADQ + 128 * PADV + 128 * PADQ) * sizeof(float);
    if (!attr_set) {
        cudaFuncSetAttribute(attn_kernel,
                             cudaFuncAttributeMaxDynamicSharedMemorySize, (int)smem);
        attr_set = true;
    }
    dim3 ga(SS / 128, BB * HH);       // (16, 32)
    attn_kernel<<<ga, 256, smem>>>();

    // Output projection (token-major)
    gemm_kernel<<<gb, 256>>>(attn_ptr, Wp, bp, proj_ptr, 1.0f, 0);

    // Residual + LayerNorm
    ln_kernel<<<NTOK, 256>>>(x, gamma, beta, out);
}

// round 6
// speedup vs baseline: 4.0665x; 1.0373x over previous
#include <cuda_runtime.h>
#include <cstdint>

// Problem constants
#define BB 2
#define SS 2048
#define DD 1024
#define HH 16
#define HD 64
#define NTOK (BB*SS)          // 4096
#define EPS 1e-5f
#define LOG2E 1.44269504088896340736f

typedef unsigned long long ull;

// ---------------- f32x2 packed-math helpers (SASS FFMA2 path) --------------
__device__ __forceinline__ ull pk2(float x, float y) {
    ull r; asm("mov.b64 %0, {%1, %2};" : "=l"(r) : "f"(x), "f"(y)); return r;
}
__device__ __forceinline__ ull ffma2(ull a, ull b, ull c) {
    ull d; asm("fma.rn.f32x2 %0, %1, %2, %3;" : "=l"(d) : "l"(a), "l"(b), "l"(c)); return d;
}
__device__ __forceinline__ ull fmul2(ull a, ull b) {
    ull d; asm("mul.rn.f32x2 %0, %1, %2;" : "=l"(d) : "l"(a), "l"(b)); return d;
}
__device__ __forceinline__ float2 up2(ull v) {
    float2 f; asm("mov.b64 {%0, %1}, %2;" : "=f"(f.x), "=f"(f.y) : "l"(v)); return f;
}
__device__ __forceinline__ float fexp2(float x) {
    float y; asm("ex2.approx.ftz.f32 %0, %1;" : "=f"(y) : "f"(x)); return y;
}

// ---------------- device scratch (allocation-free rule: device globals) ----
__device__ float g_q[(size_t)BB*HH*SS*HD];     // head-major, Q pre-scaled 0.125*log2e
__device__ float g_k[(size_t)BB*HH*SS*HD];
__device__ float g_v[(size_t)BB*HH*SS*HD];
__device__ float g_attn[(size_t)NTOK*DD];      // token-major
__device__ float g_proj[(size_t)NTOK*DD];

// ---------------------------------------------------------------------------
// Tiled SGEMM with FFMA2: C[4096,1024] = A @ W + bias (*scale)
// BM=BN=128, BK=8, 256 threads, 8 rows x 8 cols per thread.
// blockIdx.z selects (W, bias, C, scale) -> fused QKV in one launch.
// ---------------------------------------------------------------------------
__global__ void __launch_bounds__(256, 2) gemm_kernel(
    const float* __restrict__ A,
    const float* __restrict__ W0, const float* __restrict__ W1, const float* __restrict__ W2,
    const float* __restrict__ b0, const float* __restrict__ b1, const float* __restrict__ b2,
    float* __restrict__ C0, float* __restrict__ C1, float* __restrict__ C2,
    float s0, float s1, float s2, int head_major)
{
    __shared__ float As[8][128];
    __shared__ float Bs[8][128];

    const int z = blockIdx.z;
    const float* W    = (z == 0) ? W0 : (z == 1) ? W1 : W2;
    const float* bias = (z == 0) ? b0 : (z == 1) ? b1 : b2;
    float*       C    = (z == 0) ? C0 : (z == 1) ? C1 : C2;
    const float scale = (z == 0) ? s0 : (z == 1) ? s1 : s2;

    const int tid  = threadIdx.x;
    const int brow = blockIdx.y * 128;
    const int bcol = blockIdx.x * 128;

    const int arow   = tid >> 1;
    const int acol   = (tid & 1) * 4;
    const int brow_l = tid >> 5;
    const int bcol_l = (tid & 31) * 4;

    const int tx = tid & 15;
    const int ty = tid >> 4;

    ull acc[8][4];
#pragma unroll
    for (int i = 0; i < 8; i++)
#pragma unroll
        for (int j = 0; j < 4; j++) acc[i][j] = 0ULL;

    const float* Aptr = A + (size_t)(brow + arow) * 1024 + acol;
    const float* Bptr = W + (size_t)brow_l * 1024 + bcol + bcol_l;

    float4 av = *(const float4*)(Aptr);
    float4 bv = *(const float4*)(Bptr);

    for (int k0 = 0; k0 < 1024; k0 += 8) {
        As[acol + 0][arow] = av.x;
        As[acol + 1][arow] = av.y;
        As[acol + 2][arow] = av.z;
        As[acol + 3][arow] = av.w;
        *(float4*)&Bs[brow_l][bcol_l] = bv;
        __syncthreads();

        if (k0 + 8 < 1024) {
            Aptr += 8;
            Bptr += (size_t)8 * 1024;
            av = *(const float4*)(Aptr);
            bv = *(const float4*)(Bptr);
        }

#pragma unroll
        for (int kk = 0; kk < 8; kk++) {
            float a[8];
            *(float4*)&a[0] = *(const float4*)&As[kk][ty * 8];
            *(float4*)&a[4] = *(const float4*)&As[kk][ty * 8 + 4];
            ulonglong2 b0v = *(const ulonglong2*)&Bs[kk][tx * 4];
            ulonglong2 b1v = *(const ulonglong2*)&Bs[kk][64 + tx * 4];
#pragma unroll
            for (int i = 0; i < 8; i++) {
                ull ad = pk2(a[i], a[i]);
                acc[i][0] = ffma2(ad, b0v.x, acc[i][0]);
                acc[i][1] = ffma2(ad, b0v.y, acc[i][1]);
                acc[i][2] = ffma2(ad, b1v.x, acc[i][2]);
                acc[i][3] = ffma2(ad, b1v.y, acc[i][3]);
            }
        }
        __syncthreads();
    }

    const int col0 = bcol + tx * 4;
    const int col1 = col0 + 64;
    float4 bb0 = *(const float4*)&bias[col0];
    float4 bb1 = *(const float4*)&bias[col1];

#pragma unroll
    for (int i = 0; i < 8; i++) {
        const int row  = brow + ty * 8 + i;
        const int bidx = row >> 11;
        const int srow = row & 2047;
        float2 p0 = up2(acc[i][0]), p1 = up2(acc[i][1]);
        float2 p2 = up2(acc[i][2]), p3 = up2(acc[i][3]);
        float4 o0, o1;
        o0.x = (p0.x + bb0.x) * scale; o0.y = (p0.y + bb0.y) * scale;
        o0.z = (p1.x + bb0.z) * scale; o0.w = (p1.y + bb0.w) * scale;
        o1.x = (p2.x + bb1.x) * scale; o1.y = (p2.y + bb1.y) * scale;
        o1.z = (p3.x + bb1.z) * scale; o1.w = (p3.y + bb1.w) * scale;
        if (head_major) {
            const int h0 = col0 >> 6, hd0 = col0 & 63;
            const int h1 = col1 >> 6, hd1 = col1 & 63;
            *(float4*)(C + ((((size_t)bidx * HH + h0) * SS + srow) * HD + hd0)) = o0;
            *(float4*)(C + ((((size_t)bidx * HH + h1) * SS + srow) * HD + hd1)) = o1;
        } else {
            *(float4*)&C[(size_t)row * 1024 + col0] = o0;
            *(float4*)&C[(size_t)row * 1024 + col1] = o1;
        }
    }
}

// ---------------------------------------------------------------------------
// Flash attention v3: q tile 128, key tile 64, 2 CTAs/SM (smem ~100KB).
// 256 threads: tx = t&15 (key/dcol quarter), ty = t>>4 (8 rows each).
// Scores paired over q-row-pairs (FFMA2); softmax in exp2 domain
// (Q pre-scaled by 0.125*log2e); PV paired over rows.
// ---------------------------------------------------------------------------
#define KT 64
#define PADQ 132
#define PADK 68
#define ATTN_SMEM ((64*PADQ + 64*PADK + KT*PADK + KT*PADQ) * 4)   // 102400 B

__global__ void __launch_bounds__(256, 2) attn_kernel()
{
    extern __shared__ float sm[];
    float* sQT = sm;                                  // [64][PADQ] d-major, col=q-row
    float* sKT = sm + 64 * PADQ;                      // [64][PADK] d-major, col=key
    float* sV  = sm + 64 * PADQ + 64 * PADK;          // [KT][PADK] key-major
    float* sPT = sm + 64 * PADQ + 64 * PADK + KT * PADK;  // [KT][PADQ] key-major, col=q-row

    const int bh = blockIdx.y;
    const int qt = blockIdx.x;
    const int t  = threadIdx.x;
    const int tx = t & 15;
    const int ty = t >> 4;

    // ---- load Q transposed: sQT[d][row] ----
    const float* qb = g_q + ((size_t)bh * SS + qt * 128) * HD;
    for (int i = t; i < 2048; i += 256) {
        const int d4  = (i >> 7) << 2;
        const int row = i & 127;
        float4 v = *(const float4*)&qb[row * HD + d4];
        sQT[(d4 + 0) * PADQ + row] = v.x;
        sQT[(d4 + 1) * PADQ + row] = v.y;
        sQT[(d4 + 2) * PADQ + row] = v.z;
        sQT[(d4 + 3) * PADQ + row] = v.w;
    }

    ull accpv[4][4];
#pragma unroll
    for (int i = 0; i < 4; i++)
#pragma unroll
        for (int j = 0; j < 4; j++) accpv[i][j] = 0ULL;

    float m[8], l[8];
#pragma unroll
    for (int r = 0; r < 8; r++) { m[r] = -1e30f; l[r] = 0.f; }

    const float* kb = g_k + (size_t)bh * SS * HD;
    const float* vb = g_v + (size_t)bh * SS * HD;

    for (int kt0 = 0; kt0 < SS; kt0 += KT) {
        __syncthreads();   // prev tile done with sKT/sV/sPT
        // K transposed: sKT[d][key], 64 keys
        for (int i = t; i < 1024; i += 256) {
            const int d4 = (i >> 6) << 2;
            const int c  = i & 63;
            float4 v = *(const float4*)&kb[(size_t)(kt0 + c) * HD + d4];
            sKT[(d4 + 0) * PADK + c] = v.x;
            sKT[(d4 + 1) * PADK + c] = v.y;
            sKT[(d4 + 2) * PADK + c] = v.z;
            sKT[(d4 + 3) * PADK + c] = v.w;
        }
        // V: sV[key][d]
        for (int i = t; i < 1024; i += 256) {
            const int c  = i >> 4;
            const int d4 = (i & 15) << 2;
            *(float4*)&sV[c * PADK + d4] = *(const float4*)&vb[(size_t)(kt0 + c) * HD + d4];
        }
        __syncthreads();

        // ---- scores: acc[rp][j] = rowpair(ty*8+2rp) x key(tx+16j) ----
        ull acc[4][4];
#pragma unroll
        for (int i = 0; i < 4; i++)
#pragma unroll
            for (int j = 0; j < 4; j++) acc[i][j] = 0ULL;

#pragma unroll 4
        for (int d = 0; d < 64; d++) {
            const float* qrow = &sQT[d * PADQ + ty * 8];
            ull qp0 = *(const ull*)&qrow[0];
            ull qp1 = *(const ull*)&qrow[2];
            ull qp2 = *(const ull*)&qrow[4];
            ull qp3 = *(const ull*)&qrow[6];
            const float* krow = &sKT[d * PADK + tx];
#pragma unroll
            for (int j = 0; j < 4; j++) {
                const float kvj = krow[16 * j];
                ull kd = pk2(kvj, kvj);
                acc[0][j] = ffma2(qp0, kd, acc[0][j]);
                acc[1][j] = ffma2(qp1, kd, acc[1][j]);
                acc[2][j] = ffma2(qp2, kd, acc[2][j]);
                acc[3][j] = ffma2(qp3, kd, acc[3][j]);
            }
        }

        // unpack scores (log2-domain)
        float sc[8][4];
#pragma unroll
        for (int rp = 0; rp < 4; rp++)
#pragma unroll
            for (int j = 0; j < 4; j++) {
                float2 f = up2(acc[rp][j]);
                sc[2 * rp + 0][j] = f.x;
                sc[2 * rp + 1][j] = f.y;
            }

        // ---- online softmax per row (keys over 16 tx lanes), base-2 ----
        float alpha[8];
#pragma unroll
        for (int r = 0; r < 8; r++) {
            float tm = fmaxf(fmaxf(sc[r][0], sc[r][1]), fmaxf(sc[r][2], sc[r][3]));
            tm = fmaxf(tm, __shfl_xor_sync(0xffffffffu, tm, 1));
            tm = fmaxf(tm, __shfl_xor_sync(0xffffffffu, tm, 2));
            tm = fmaxf(tm, __shfl_xor_sync(0xffffffffu, tm, 4));
            tm = fmaxf(tm, __shfl_xor_sync(0xffffffffu, tm, 8));
            const float mn = fmaxf(m[r], tm);
            alpha[r] = fexp2(m[r] - mn);
            m[r] = mn;
            float ps = 0.f;
#pragma unroll
            for (int j = 0; j < 4; j++) {
                sc[r][j] = fexp2(sc[r][j] - mn);
                ps += sc[r][j];
            }
            ps += __shfl_xor_sync(0xffffffffu, ps, 1);
            ps += __shfl_xor_sync(0xffffffffu, ps, 2);
            ps += __shfl_xor_sync(0xffffffffu, ps, 4);
            ps += __shfl_xor_sync(0xffffffffu, ps, 8);
            l[r] = l[r] * alpha[r] + ps;
        }

        // rescale running PV accumulators
#pragma unroll
        for (int rp = 0; rp < 4; rp++) {
            ull ap = pk2(alpha[2 * rp], alpha[2 * rp + 1]);
#pragma unroll
            for (int dc = 0; dc < 4; dc++)
                accpv[rp][dc] = fmul2(accpv[rp][dc], ap);
        }

        // store P key-major: sPT[key][row] (read back within same warp only)
#pragma unroll
        for (int j = 0; j < 4; j++) {
            const int key = tx + 16 * j;
            float4 v0 = make_float4(sc[0][j], sc[1][j], sc[2][j], sc[3][j]);
            float4 v1 = make_float4(sc[4][j], sc[5][j], sc[6][j], sc[7][j]);
            *(float4*)&sPT[key * PADQ + ty * 8]     = v0;
            *(float4*)&sPT[key * PADQ + ty * 8 + 4] = v1;
        }
        __syncwarp();

        // ---- PV: accpv[rp][dc] += P[rowpair][c] * V[c][dcol] ----
#pragma unroll 4
        for (int c = 0; c < KT; c++) {
            const float* prow = &sPT[c * PADQ + ty * 8];
            ull pp0 = *(const ull*)&prow[0];
            ull pp1 = *(const ull*)&prow[2];
            ull pp2 = *(const ull*)&prow[4];
            ull pp3 = *(const ull*)&prow[6];
            float4 vv = *(const float4*)&sV[c * PADK + tx * 4];
            ull v0 = pk2(vv.x, vv.x);
            ull v1 = pk2(vv.y, vv.y);
            ull v2 = pk2(vv.z, vv.z);
            ull v3 = pk2(vv.w, vv.w);
            accpv[0][0] = ffma2(pp0, v0, accpv[0][0]);
            accpv[0][1] = ffma2(pp0, v1, accpv[0][1]);
            accpv[0][2] = ffma2(pp0, v2, accpv[0][2]);
            accpv[0][3] = ffma2(pp0, v3, accpv[0][3]);
            accpv[1][0] = ffma2(pp1, v0, accpv[1][0]);
            accpv[1][1] = ffma2(pp1, v1, accpv[1][1]);
            accpv[1][2] = ffma2(pp1, v2, accpv[1][2]);
            accpv[1][3] = ffma2(pp1, v3, accpv[1][3]);
            accpv[2][0] = ffma2(pp2, v0, accpv[2][0]);
            accpv[2][1] = ffma2(pp2, v1, accpv[2][1]);
            accpv[2][2] = ffma2(pp2, v2, accpv[2][2]);
            accpv[2][3] = ffma2(pp2, v3, accpv[2][3]);
            accpv[3][0] = ffma2(pp3, v0, accpv[3][0]);
            accpv[3][1] = ffma2(pp3, v1, accpv[3][1]);
            accpv[3][2] = ffma2(pp3, v2, accpv[3][2]);
            accpv[3][3] = ffma2(pp3, v3, accpv[3][3]);
        }
    }

    // ---- normalize + write out (token-major, merge heads) ----
    const int b = bh >> 4, h = bh & 15;
#pragma unroll
    for (int rp = 0; rp < 4; rp++) {
        const float invE = 1.f / l[2 * rp];
        const float invO = 1.f / l[2 * rp + 1];
        float2 o0 = up2(accpv[rp][0]);
        float2 o1 = up2(accpv[rp][1]);
        float2 o2 = up2(accpv[rp][2]);
        float2 o3 = up2(accpv[rp][3]);
        float4 oe = make_float4(o0.x * invE, o1.x * invE, o2.x * invE, o3.x * invE);
        float4 oo = make_float4(o0.y * invO, o1.y * invO, o2.y * invO, o3.y * invO);
        const int r0 = qt * 128 + ty * 8 + 2 * rp;
        float* p0 = g_attn + (size_t)(b * SS + r0) * DD + h * HD + tx * 4;
        *(float4*)p0        = oe;
        *(float4*)(p0 + DD) = oo;
    }
}

// ---------------------------------------------------------------------------
// Residual + LayerNorm: 1 block per token row.
// ---------------------------------------------------------------------------
__global__ void __launch_bounds__(256) ln_kernel(
    const float* __restrict__ x, const float* __restrict__ gamma,
    const float* __restrict__ beta, float* __restrict__ out)
{
    __shared__ float ssum[8], ssq[8];
    const int row = blockIdx.x;
    const int t = threadIdx.x;

    float4 xv = ((const float4*)(x      + (size_t)row * DD))[t];
    float4 pv = ((const float4*)(g_proj + (size_t)row * DD))[t];
    float4 y;
    y.x = xv.x + pv.x; y.y = xv.y + pv.y; y.z = xv.z + pv.z; y.w = xv.w + pv.w;

    float s  = y.x + y.y + y.z + y.w;
    float sq = y.x * y.x + y.y * y.y + y.z * y.z + y.w * y.w;
#pragma unroll
    for (int off = 16; off > 0; off >>= 1) {
        s  += __shfl_xor_sync(0xffffffffu, s,  off);
        sq += __shfl_xor_sync(0xffffffffu, sq, off);
    }
    const int warp = t >> 5;
    if ((t & 31) == 0) { ssum[warp] = s; ssq[warp] = sq; }
    __syncthreads();
    float tot = 0.f, totq = 0.f;
#pragma unroll
    for (int i = 0; i < 8; i++) { tot += ssum[i]; totq += ssq[i]; }

    const float mu   = tot * (1.f / DD);
    const float var  = totq * (1.f / DD) - mu * mu;
    const float rstd = rsqrtf(var + EPS);

    float4 g = ((const float4*)gamma)[t];
    float4 b = ((const float4*)beta)[t];
    float4 o;
    o.x = (y.x - mu) * rstd * g.x + b.x;
    o.y = (y.y - mu) * rstd * g.y + b.y;
    o.z = (y.z - mu) * rstd * g.z + b.z;
    o.w = (y.w - mu) * rstd * g.w + b.w;
    ((float4*)(out + (size_t)row * DD))[t] = o;
}

// ---------------------------------------------------------------------------
extern "C" void kernel_launch(void* const* d_in, const int* in_sizes, int n_in,
                              void* d_out, int out_size)
{
    const float* x     = (const float*)d_in[0];
    const float* Wq    = (const float*)d_in[1];
    const float* bq    = (const float*)d_in[2];
    const float* Wk    = (const float*)d_in[3];
    const float* bk    = (const float*)d_in[4];
    const float* Wv    = (const float*)d_in[5];
    const float* bv    = (const float*)d_in[6];
    const float* Wp    = (const float*)d_in[7];
    const float* bp    = (const float*)d_in[8];
    const float* gamma = (const float*)d_in[9];
    const float* beta  = (const float*)d_in[10];
    float* out = (float*)d_out;

    float *q_ptr, *k_ptr, *v_ptr, *attn_ptr, *proj_ptr;
    cudaGetSymbolAddress((void**)&q_ptr,    g_q);
    cudaGetSymbolAddress((void**)&k_ptr,    g_k);
    cudaGetSymbolAddress((void**)&v_ptr,    g_v);
    cudaGetSymbolAddress((void**)&attn_ptr, g_attn);
    cudaGetSymbolAddress((void**)&proj_ptr, g_proj);

    static bool attr_set = false;
    if (!attr_set) {
        cudaFuncSetAttribute(attn_kernel,
                             cudaFuncAttributeMaxDynamicSharedMemorySize, ATTN_SMEM);
        attr_set = true;
    }

    // Fused QKV projections (one launch, z selects weight set).
    // Q pre-scaled by 1/sqrt(HD) * log2(e) for base-2 softmax.
    const float qscale = 0.125f * LOG2E;
    dim3 gb(DD / 128, NTOK / 128, 3);   // (8, 32, 3)
    gemm_kernel<<<gb, 256>>>(x, Wq, Wk, Wv, bq, bk, bv,
                             q_ptr, k_ptr, v_ptr, qscale, 1.0f, 1.0f, 1);

    // Attention
    dim3 ga(SS / 128, BB * HH);         // (16, 32)
    attn_kernel<<<ga, 256, ATTN_SMEM>>>();

    // Output projection (token-major)
    dim3 gp(DD / 128, NTOK / 128, 1);
    gemm_kernel<<<gp, 256>>>(attn_ptr, Wp, Wp, Wp, bp, bp, bp,
                             proj_ptr, proj_ptr, proj_ptr, 1.0f, 1.0f, 1.0f, 0);

    // Residual + LayerNorm
    ln_kernel<<<NTOK, 256>>>(x, gamma, beta, out);
}

// round 7
// speedup vs baseline: 5.2046x; 1.2799x over previous
#include <cuda_runtime.h>
#include <cuda_bf16.h>
#include <cstdint>

// Problem constants
#define BB 2
#define SS 2048
#define DD 1024
#define HH 16
#define HD 64
#define NTOK (BB*SS)          // 4096
#define EPS 1e-5f
#define LOG2E 1.44269504088896340736f

typedef unsigned long long ull;

// ---------------- f32x2 packed-math helpers (SASS FFMA2 path) --------------
__device__ __forceinline__ ull pk2(float x, float y) {
    ull r; asm("mov.b64 %0, {%1, %2};" : "=l"(r) : "f"(x), "f"(y)); return r;
}
__device__ __forceinline__ ull ffma2(ull a, ull b, ull c) {
    ull d; asm("fma.rn.f32x2 %0, %1, %2, %3;" : "=l"(d) : "l"(a), "l"(b), "l"(c)); return d;
}
__device__ __forceinline__ ull fmul2(ull a, ull b) {
    ull d; asm("mul.rn.f32x2 %0, %1, %2;" : "=l"(d) : "l"(a), "l"(b)); return d;
}
__device__ __forceinline__ float2 up2(ull v) {
    float2 f; asm("mov.b64 {%0, %1}, %2;" : "=f"(f.x), "=f"(f.y) : "l"(v)); return f;
}
__device__ __forceinline__ float fexp2(float x) {
    float y; asm("ex2.approx.ftz.f32 %0, %1;" : "=f"(y) : "f"(x)); return y;
}

// ---------------- mma.sync / ldmatrix helpers (base-ISA tensor cores) ------
__device__ __forceinline__ uint32_t smem_u32(const void* p) {
    uint32_t a;
    asm("{ .reg .u64 t; cvta.to.shared.u64 t, %1; cvt.u32.u64 %0, t; }" : "=r"(a) : "l"(p));
    return a;
}
__device__ __forceinline__ void ldm4(uint32_t* r, uint32_t addr) {
    asm volatile("ldmatrix.sync.aligned.m8n8.x4.shared.b16 {%0,%1,%2,%3}, [%4];"
        : "=r"(r[0]), "=r"(r[1]), "=r"(r[2]), "=r"(r[3]) : "r"(addr));
}
__device__ __forceinline__ void mma16816(float* c, const uint32_t* a, const uint32_t* b) {
    asm volatile("mma.sync.aligned.m16n8k16.row.col.f32.bf16.bf16.f32 "
        "{%0,%1,%2,%3}, {%4,%5,%6,%7}, {%8,%9}, {%0,%1,%2,%3};"
        : "+f"(c[0]), "+f"(c[1]), "+f"(c[2]), "+f"(c[3])
        : "r"(a[0]), "r"(a[1]), "r"(a[2]), "r"(a[3]), "r"(b[0]), "r"(b[1]));
}

// ---------------- device scratch (allocation-free rule: device globals) ----
__device__ float g_q[(size_t)BB*HH*SS*HD];     // head-major, Q pre-scaled 0.125*log2e
__device__ float g_k[(size_t)BB*HH*SS*HD];
__device__ float g_v[(size_t)BB*HH*SS*HD];
__device__ float g_attn[(size_t)NTOK*DD];      // token-major
__device__ float g_proj[(size_t)NTOK*DD];

// split-bf16 operands
__device__ __align__(16) __nv_bfloat16 g_xhi[(size_t)NTOK*DD];
__device__ __align__(16) __nv_bfloat16 g_xlo[(size_t)NTOK*DD];
__device__ __align__(16) __nv_bfloat16 g_ahi[(size_t)NTOK*DD];
__device__ __align__(16) __nv_bfloat16 g_alo[(size_t)NTOK*DD];
// transposed weights WT[n][k], hi/lo
__device__ __align__(16) __nv_bfloat16 g_wq_hi[(size_t)DD*DD];
__device__ __align__(16) __nv_bfloat16 g_wq_lo[(size_t)DD*DD];
__device__ __align__(16) __nv_bfloat16 g_wk_hi[(size_t)DD*DD];
__device__ __align__(16) __nv_bfloat16 g_wk_lo[(size_t)DD*DD];
__device__ __align__(16) __nv_bfloat16 g_wv_hi[(size_t)DD*DD];
__device__ __align__(16) __nv_bfloat16 g_wv_lo[(size_t)DD*DD];
__device__ __align__(16) __nv_bfloat16 g_wp_hi[(size_t)DD*DD];
__device__ __align__(16) __nv_bfloat16 g_wp_lo[(size_t)DD*DD];

// ---------------------------------------------------------------------------
// Elementwise fp32 -> (bf16 hi, bf16 lo) split.
// ---------------------------------------------------------------------------
__global__ void __launch_bounds__(256) cvt_split_kernel(
    const float* __restrict__ in, __nv_bfloat16* __restrict__ hi,
    __nv_bfloat16* __restrict__ lo)
{
    const int i = blockIdx.x * 256 + threadIdx.x;
    float4 v = ((const float4*)in)[i];
    __nv_bfloat16 h0 = __float2bfloat16(v.x);
    __nv_bfloat16 h1 = __float2bfloat16(v.y);
    __nv_bfloat16 h2 = __float2bfloat16(v.z);
    __nv_bfloat16 h3 = __float2bfloat16(v.w);
    __nv_bfloat16 l0 = __float2bfloat16(v.x - __bfloat162float(h0));
    __nv_bfloat16 l1 = __float2bfloat16(v.y - __bfloat162float(h1));
    __nv_bfloat16 l2 = __float2bfloat16(v.z - __bfloat162float(h2));
    __nv_bfloat16 l3 = __float2bfloat16(v.w - __bfloat162float(h3));
    __nv_bfloat162* hp = (__nv_bfloat162*)hi;
    __nv_bfloat162* lp = (__nv_bfloat162*)lo;
    hp[2*i]   = __nv_bfloat162(h0, h1);
    hp[2*i+1] = __nv_bfloat162(h2, h3);
    lp[2*i]   = __nv_bfloat162(l0, l1);
    lp[2*i+1] = __nv_bfloat162(l2, l3);
}

// ---------------------------------------------------------------------------
// W[1024x1024] fp32 (k-major rows) -> WT hi/lo bf16 [n][k] (transposed).
// ---------------------------------------------------------------------------
__global__ void __launch_bounds__(256) wtrans_kernel(
    const float* __restrict__ W, __nv_bfloat16* __restrict__ Thi,
    __nv_bfloat16* __restrict__ Tlo)
{
    __shared__ float tile[32][33];
    const int tx = threadIdx.x, ty = threadIdx.y;
    const int n0 = blockIdx.x * 32, k0 = blockIdx.y * 32;
#pragma unroll
    for (int r = ty; r < 32; r += 8)
        tile[r][tx] = W[(size_t)(k0 + r) * DD + n0 + tx];   // tile[k][n]
    __syncthreads();
#pragma unroll
    for (int r = ty; r < 32; r += 8) {
        const int n = n0 + r, k = k0 + tx;
        const float v = tile[tx][r];
        __nv_bfloat16 h = __float2bfloat16(v);
        __nv_bfloat16 l = __float2bfloat16(v - __bfloat162float(h));
        Thi[(size_t)n * DD + k] = h;
        Tlo[(size_t)n * DD + k] = l;
    }
}

// ---------------------------------------------------------------------------
// Tensor-core GEMM (legacy mma.sync, split-bf16, fp32 accumulate):
// C[4096,1024] = A @ W + bias (*scale).  A as hi/lo bf16 [M,K] row-major;
// W as transposed hi/lo bf16 [N,K].  blockIdx.z selects weight set (QKV fuse).
// CTA tile 128x128, 512 threads = 16 warps in 4x4 grid, warp tile 32x32.
// K staged in chunks of 128 (smem rows padded to 136 halfs = 272B stride:
// 272 % 128 = 16 -> 8-row ldmatrix reads hit 8 distinct bank groups).
// 3 MMAs per fragment pair: hihi + hilo + lohi.
// ---------------------------------------------------------------------------
#define KCH 128
#define LDT 136                         // halfs per smem row
#define TILE_HALFS (128 * LDT)          // 17408
#define TILE_BYTES (TILE_HALFS * 2)     // 34816
#define GEMM_SMEM (4 * TILE_BYTES)      // 139264

__global__ void __launch_bounds__(512) gemm_tc_kernel(
    const __nv_bfloat16* __restrict__ Ahi, const __nv_bfloat16* __restrict__ Alo,
    const __nv_bfloat16* __restrict__ Wq_hi, const __nv_bfloat16* __restrict__ Wq_lo,
    const __nv_bfloat16* __restrict__ Wk_hi, const __nv_bfloat16* __restrict__ Wk_lo,
    const __nv_bfloat16* __restrict__ Wv_hi, const __nv_bfloat16* __restrict__ Wv_lo,
    const float* __restrict__ b0, const float* __restrict__ b1, const float* __restrict__ b2,
    float* __restrict__ C0, float* __restrict__ C1, float* __restrict__ C2,
    float s0, float s1, float s2, int head_major)
{
    extern __shared__ __nv_bfloat16 smem[];
    __nv_bfloat16* sAhi = smem;
    __nv_bfloat16* sAlo = smem + TILE_HALFS;
    __nv_bfloat16* sBhi = smem + 2 * TILE_HALFS;
    __nv_bfloat16* sBlo = smem + 3 * TILE_HALFS;

    const int z = blockIdx.z;
    const __nv_bfloat16* Bhi = (z == 0) ? Wq_hi : (z == 1) ? Wk_hi : Wv_hi;
    const __nv_bfloat16* Blo = (z == 0) ? Wq_lo : (z == 1) ? Wk_lo : Wv_lo;
    const float* bias = (z == 0) ? b0 : (z == 1) ? b1 : b2;
    float*       C    = (z == 0) ? C0 : (z == 1) ? C1 : C2;
    const float scale = (z == 0) ? s0 : (z == 1) ? s1 : s2;

    const int tid  = threadIdx.x;
    const int wid  = tid >> 5;
    const int lane = tid & 31;
    const int wm   = wid >> 2;          // 0..3 (m direction)
    const int wn   = wid & 3;           // 0..3 (n direction)
    const int brow = blockIdx.y * 128;
    const int bcol = blockIdx.x * 128;

    float c[2][4][4];
#pragma unroll
    for (int i = 0; i < 2; i++)
#pragma unroll
        for (int j = 0; j < 4; j++)
#pragma unroll
            for (int q = 0; q < 4; q++) c[i][j][q] = 0.f;

    // ldmatrix lane address components (bytes)
    // A (m16k16 x4): row = (l&7) + ((l>>3)&1)*8 ; k-offset = (l>>4)*8
    const uint32_t aRow = (lane & 7) + ((lane >> 3) & 1) * 8;
    const uint32_t aKof = (lane >> 4) * 8;
    // B (two n8k16 frags per x4): n-row = (l&7) + (l>>4)*8 ; k-offset = ((l>>3)&1)*8
    const uint32_t bRow = (lane & 7) + (lane >> 4) * 8;
    const uint32_t bKof = ((lane >> 3) & 1) * 8;

    const uint32_t sbase = smem_u32(smem);
    const uint32_t aHiB = sbase + ((32 * wm + aRow) * LDT + aKof) * 2;
    const uint32_t aLoB = aHiB + TILE_BYTES;
    const uint32_t bHiB = sbase + 2u * TILE_BYTES + ((32 * wn + bRow) * LDT + bKof) * 2;
    const uint32_t bLoB = bHiB + TILE_BYTES;

    for (int kc = 0; kc < DD; kc += KCH) {
        __syncthreads();   // previous chunk's MMAs done with smem
        // ---- stage A(hi,lo) rows brow..+127, B(hi,lo) rows bcol..+127 ----
#pragma unroll
        for (int rep = 0; rep < 4; rep++) {
            const int idx = tid + rep * 512;          // 0..2047
            const int row = idx >> 4;                 // 0..127
            const int c8  = idx & 15;                 // 16B unit within 128 halfs
            const size_t goff = (size_t)row * DD + kc + c8 * 8;
            const uint32_t soff = row * LDT + c8 * 8;
            *(uint4*)(sAhi + soff) = *(const uint4*)(Ahi + (size_t)brow * DD + goff);
            *(uint4*)(sAlo + soff) = *(const uint4*)(Alo + (size_t)brow * DD + goff);
            *(uint4*)(sBhi + soff) = *(const uint4*)(Bhi + (size_t)bcol * DD + goff);
            *(uint4*)(sBlo + soff) = *(const uint4*)(Blo + (size_t)bcol * DD + goff);
        }
        __syncthreads();

        // ---- 8 k16-steps over this chunk ----
#pragma unroll
        for (int s = 0; s < 8; s++) {
            uint32_t ah[2][4], al[2][4], bh[4][2], bl[4][2];
            const uint32_t sb = s * 32;               // 16 halfs = 32 bytes
            ldm4(ah[0], aHiB + sb);
            ldm4(ah[1], aHiB + 16 * LDT * 2 + sb);
            ldm4(al[0], aLoB + sb);
            ldm4(al[1], aLoB + 16 * LDT * 2 + sb);
            ldm4(&bh[0][0], bHiB + sb);
            ldm4(&bh[2][0], bHiB + 16 * LDT * 2 + sb);
            ldm4(&bl[0][0], bLoB + sb);
            ldm4(&bl[2][0], bLoB + 16 * LDT * 2 + sb);
#pragma unroll
            for (int i = 0; i < 2; i++)
#pragma unroll
                for (int j = 0; j < 4; j++) {
                    mma16816(c[i][j], ah[i], bh[j]);
                    mma16816(c[i][j], ah[i], bl[j]);
                    mma16816(c[i][j], al[i], bh[j]);
                }
        }
    }

    // ---- epilogue: c regs -> (row, col) pairs; bias, scale, scatter ----
    const int rbase = brow + 32 * wm + (lane >> 2);
    const int cbase = bcol + 32 * wn + 2 * (lane & 3);
#pragma unroll
    for (int i = 0; i < 2; i++) {
#pragma unroll
        for (int j = 0; j < 4; j++) {
            const int col = cbase + 8 * j;
            const float2 bb = *(const float2*)&bias[col];
#pragma unroll
            for (int half = 0; half < 2; half++) {    // c0/c1 then c2/c3 (row+8)
                const int row = rbase + 16 * i + 8 * half;
                float2 o;
                o.x = (c[i][j][2 * half + 0] + bb.x) * scale;
                o.y = (c[i][j][2 * half + 1] + bb.y) * scale;
                const int bidx = row >> 11, srow = row & 2047;
                if (head_major) {
                    const int h = col >> 6, hd = col & 63;
                    *(float2*)(C + ((((size_t)bidx * HH + h) * SS + srow) * HD + hd)) = o;
                } else {
                    *(float2*)&C[(size_t)row * DD + col] = o;
                }
            }
        }
    }
}

// ---------------------------------------------------------------------------
// Flash attention (round-5, passing): q tile 128, key tile 64, FFMA2 fp32,
// base-2 softmax (Q pre-scaled by 0.125*log2e).
// ---------------------------------------------------------------------------
#define KT 64
#define PADQ 132
#define PADK 68
#define ATTN_SMEM ((64*PADQ + 64*PADK + KT*PADK + KT*PADQ) * 4)   // 102400 B

__global__ void __launch_bounds__(256, 2) attn_kernel()
{
    extern __shared__ float sm[];
    float* sQT = sm;
    float* sKT = sm + 64 * PADQ;
    float* sV  = sm + 64 * PADQ + 64 * PADK;
    float* sPT = sm + 64 * PADQ + 64 * PADK + KT * PADK;

    const int bh = blockIdx.y;
    const int qt = blockIdx.x;
    const int t  = threadIdx.x;
    const int tx = t & 15;
    const int ty = t >> 4;

    const float* qb = g_q + ((size_t)bh * SS + qt * 128) * HD;
    for (int i = t; i < 2048; i += 256) {
        const int d4  = (i >> 7) << 2;
        const int row = i & 127;
        float4 v = *(const float4*)&qb[row * HD + d4];
        sQT[(d4 + 0) * PADQ + row] = v.x;
        sQT[(d4 + 1) * PADQ + row] = v.y;
        sQT[(d4 + 2) * PADQ + row] = v.z;
        sQT[(d4 + 3) * PADQ + row] = v.w;
    }

    ull accpv[4][4];
#pragma unroll
    for (int i = 0; i < 4; i++)
#pragma unroll
        for (int j = 0; j < 4; j++) accpv[i][j] = 0ULL;

    float m[8], l[8];
#pragma unroll
    for (int r = 0; r < 8; r++) { m[r] = -1e30f; l[r] = 0.f; }

    const float* kb = g_k + (size_t)bh * SS * HD;
    const float* vb = g_v + (size_t)bh * SS * HD;

    for (int kt0 = 0; kt0 < SS; kt0 += KT) {
        __syncthreads();
        for (int i = t; i < 1024; i += 256) {
            const int d4 = (i >> 6) << 2;
            const int c  = i & 63;
            float4 v = *(const float4*)&kb[(size_t)(kt0 + c) * HD + d4];
            sKT[(d4 + 0) * PADK + c] = v.x;
            sKT[(d4 + 1) * PADK + c] = v.y;
            sKT[(d4 + 2) * PADK + c] = v.z;
            sKT[(d4 + 3) * PADK + c] = v.w;
        }
        for (int i = t; i < 1024; i += 256) {
            const int c  = i >> 4;
            const int d4 = (i & 15) << 2;
            *(float4*)&sV[c * PADK + d4] = *(const float4*)&vb[(size_t)(kt0 + c) * HD + d4];
        }
        __syncthreads();

        ull acc[4][4];
#pragma unroll
        for (int i = 0; i < 4; i++)
#pragma unroll
            for (int j = 0; j < 4; j++) acc[i][j] = 0ULL;

#pragma unroll 4
        for (int d = 0; d < 64; d++) {
            const float* qrow = &sQT[d * PADQ + ty * 8];
            ull qp0 = *(const ull*)&qrow[0];
            ull qp1 = *(const ull*)&qrow[2];
            ull qp2 = *(const ull*)&qrow[4];
            ull qp3 = *(const ull*)&qrow[6];
            const float* krow = &sKT[d * PADK + tx];
#pragma unroll
            for (int j = 0; j < 4; j++) {
                const float kvj = krow[16 * j];
                ull kd = pk2(kvj, kvj);
                acc[0][j] = ffma2(qp0, kd, acc[0][j]);
                acc[1][j] = ffma2(qp1, kd, acc[1][j]);
                acc[2][j] = ffma2(qp2, kd, acc[2][j]);
                acc[3][j] = ffma2(qp3, kd, acc[3][j]);
            }
        }

        float sc[8][4];
#pragma unroll
        for (int rp = 0; rp < 4; rp++)
#pragma unroll
            for (int j = 0; j < 4; j++) {
                float2 f = up2(acc[rp][j]);
                sc[2 * rp + 0][j] = f.x;
                sc[2 * rp + 1][j] = f.y;
            }

        float alpha[8];
#pragma unroll
        for (int r = 0; r < 8; r++) {
            float tm = fmaxf(fmaxf(sc[r][0], sc[r][1]), fmaxf(sc[r][2], sc[r][3]));
            tm = fmaxf(tm, __shfl_xor_sync(0xffffffffu, tm, 1));
            tm = fmaxf(tm, __shfl_xor_sync(0xffffffffu, tm, 2));
            tm = fmaxf(tm, __shfl_xor_sync(0xffffffffu, tm, 4));
            tm = fmaxf(tm, __shfl_xor_sync(0xffffffffu, tm, 8));
            const float mn = fmaxf(m[r], tm);
            alpha[r] = fexp2(m[r] - mn);
            m[r] = mn;
            float ps = 0.f;
#pragma unroll
            for (int j = 0; j < 4; j++) {
                sc[r][j] = fexp2(sc[r][j] - mn);
                ps += sc[r][j];
            }
            ps += __shfl_xor_sync(0xffffffffu, ps, 1);
            ps += __shfl_xor_sync(0xffffffffu, ps, 2);
            ps += __shfl_xor_sync(0xffffffffu, ps, 4);
            ps += __shfl_xor_sync(0xffffffffu, ps, 8);
            l[r] = l[r] * alpha[r] + ps;
        }

#pragma unroll
        for (int rp = 0; rp < 4; rp++) {
            ull ap = pk2(alpha[2 * rp], alpha[2 * rp + 1]);
#pragma unroll
            for (int dc = 0; dc < 4; dc++)
                accpv[rp][dc] = fmul2(accpv[rp][dc], ap);
        }

#pragma unroll
        for (int j = 0; j < 4; j++) {
            const int key = tx + 16 * j;
            float4 v0 = make_float4(sc[0][j], sc[1][j], sc[2][j], sc[3][j]);
            float4 v1 = make_float4(sc[4][j], sc[5][j], sc[6][j], sc[7][j]);
            *(float4*)&sPT[key * PADQ + ty * 8]     = v0;
            *(float4*)&sPT[key * PADQ + ty * 8 + 4] = v1;
        }
        __syncwarp();

#pragma unroll 4
        for (int c = 0; c < KT; c++) {
            const float* prow = &sPT[c * PADQ + ty * 8];
            ull pp0 = *(const ull*)&prow[0];
            ull pp1 = *(const ull*)&prow[2];
            ull pp2 = *(const ull*)&prow[4];
            ull pp3 = *(const ull*)&prow[6];
            float4 vv = *(const float4*)&sV[c * PADK + tx * 4];
            ull v0 = pk2(vv.x, vv.x);
            ull v1 = pk2(vv.y, vv.y);
            ull v2 = pk2(vv.z, vv.z);
            ull v3 = pk2(vv.w, vv.w);
            accpv[0][0] = ffma2(pp0, v0, accpv[0][0]);
            accpv[0][1] = ffma2(pp0, v1, accpv[0][1]);
            accpv[0][2] = ffma2(pp0, v2, accpv[0][2]);
            accpv[0][3] = ffma2(pp0, v3, accpv[0][3]);
            accpv[1][0] = ffma2(pp1, v0, accpv[1][0]);
            accpv[1][1] = ffma2(pp1, v1, accpv[1][1]);
            accpv[1][2] = ffma2(pp1, v2, accpv[1][2]);
            accpv[1][3] = ffma2(pp1, v3, accpv[1][3]);
            accpv[2][0] = ffma2(pp2, v0, accpv[2][0]);
            accpv[2][1] = ffma2(pp2, v1, accpv[2][1]);
            accpv[2][2] = ffma2(pp2, v2, accpv[2][2]);
            accpv[2][3] = ffma2(pp2, v3, accpv[2][3]);
            accpv[3][0] = ffma2(pp3, v0, accpv[3][0]);
            accpv[3][1] = ffma2(pp3, v1, accpv[3][1]);
            accpv[3][2] = ffma2(pp3, v2, accpv[3][2]);
            accpv[3][3] = ffma2(pp3, v3, accpv[3][3]);
        }
    }

    const int b = bh >> 4, h = bh & 15;
#pragma unroll
    for (int rp = 0; rp < 4; rp++) {
        const float invE = 1.f / l[2 * rp];
        const float invO = 1.f / l[2 * rp + 1];
        float2 o0 = up2(accpv[rp][0]);
        float2 o1 = up2(accpv[rp][1]);
        float2 o2 = up2(accpv[rp][2]);
        float2 o3 = up2(accpv[rp][3]);
        float4 oe = make_float4(o0.x * invE, o1.x * invE, o2.x * invE, o3.x * invE);
        float4 oo = make_float4(o0.y * invO, o1.y * invO, o2.y * invO, o3.y * invO);
        const int r0 = qt * 128 + ty * 8 + 2 * rp;
        float* p0 = g_attn + (size_t)(b * SS + r0) * DD + h * HD + tx * 4;
        *(float4*)p0        = oe;
        *(float4*)(p0 + DD) = oo;
    }
}

// ---------------------------------------------------------------------------
// Residual + LayerNorm: 1 block per token row.
// ---------------------------------------------------------------------------
__global__ void __launch_bounds__(256) ln_kernel(
    const float* __restrict__ x, const float* __restrict__ gamma,
    const float* __restrict__ beta, float* __restrict__ out)
{
    __shared__ float ssum[8], ssq[8];
    const int row = blockIdx.x;
    const int t = threadIdx.x;

    float4 xv = ((const float4*)(x      + (size_t)row * DD))[t];
    float4 pv = ((const float4*)(g_proj + (size_t)row * DD))[t];
    float4 y;
    y.x = xv.x + pv.x; y.y = xv.y + pv.y; y.z = xv.z + pv.z; y.w = xv.w + pv.w;

    float s  = y.x + y.y + y.z + y.w;
    float sq = y.x * y.x + y.y * y.y + y.z * y.z + y.w * y.w;
#pragma unroll
    for (int off = 16; off > 0; off >>= 1) {
        s  += __shfl_xor_sync(0xffffffffu, s,  off);
        sq += __shfl_xor_sync(0xffffffffu, sq, off);
    }
    const int warp = t >> 5;
    if ((t & 31) == 0) { ssum[warp] = s; ssq[warp] = sq; }
    __syncthreads();
    float tot = 0.f, totq = 0.f;
#pragma unroll
    for (int i = 0; i < 8; i++) { tot += ssum[i]; totq += ssq[i]; }

    const float mu   = tot * (1.f / DD);
    const float var  = totq * (1.f / DD) - mu * mu;
    const float rstd = rsqrtf(var + EPS);

    float4 g = ((const float4*)gamma)[t];
    float4 b = ((const float4*)beta)[t];
    float4 o;
    o.x = (y.x - mu) * rstd * g.x + b.x;
    o.y = (y.y - mu) * rstd * g.y + b.y;
    o.z = (y.z - mu) * rstd * g.z + b.z;
    o.w = (y.w - mu) * rstd * g.w + b.w;
    ((float4*)(out + (size_t)row * DD))[t] = o;
}

// ---------------------------------------------------------------------------
extern "C" void kernel_launch(void* const* d_in, const int* in_sizes, int n_in,
                              void* d_out, int out_size)
{
    const float* x     = (const float*)d_in[0];
    const float* Wq    = (const float*)d_in[1];
    const float* bq    = (const float*)d_in[2];
    const float* Wk    = (const float*)d_in[3];
    const float* bk    = (const float*)d_in[4];
    const float* Wv    = (const float*)d_in[5];
    const float* bv    = (const float*)d_in[6];
    const float* Wp    = (const float*)d_in[7];
    const float* bp    = (const float*)d_in[8];
    const float* gamma = (const float*)d_in[9];
    const float* beta  = (const float*)d_in[10];
    float* out = (float*)d_out;

    float *q_ptr, *k_ptr, *v_ptr, *attn_ptr, *proj_ptr;
    cudaGetSymbolAddress((void**)&q_ptr,    g_q);
    cudaGetSymbolAddress((void**)&k_ptr,    g_k);
    cudaGetSymbolAddress((void**)&v_ptr,    g_v);
    cudaGetSymbolAddress((void**)&attn_ptr, g_attn);
    cudaGetSymbolAddress((void**)&proj_ptr, g_proj);

    __nv_bfloat16 *xhi, *xlo, *ahi, *alo;
    __nv_bfloat16 *wqh, *wql, *wkh, *wkl, *wvh, *wvl, *wph, *wpl;
    cudaGetSymbolAddress((void**)&xhi, g_xhi);
    cudaGetSymbolAddress((void**)&xlo, g_xlo);
    cudaGetSymbolAddress((void**)&ahi, g_ahi);
    cudaGetSymbolAddress((void**)&alo, g_alo);
    cudaGetSymbolAddress((void**)&wqh, g_wq_hi);
    cudaGetSymbolAddress((void**)&wql, g_wq_lo);
    cudaGetSymbolAddress((void**)&wkh, g_wk_hi);
    cudaGetSymbolAddress((void**)&wkl, g_wk_lo);
    cudaGetSymbolAddress((void**)&wvh, g_wv_hi);
    cudaGetSymbolAddress((void**)&wvl, g_wv_lo);
    cudaGetSymbolAddress((void**)&wph, g_wp_hi);
    cudaGetSymbolAddress((void**)&wpl, g_wp_lo);

    static bool attr_set = false;
    if (!attr_set) {
        cudaFuncSetAttribute(gemm_tc_kernel,
                             cudaFuncAttributeMaxDynamicSharedMemorySize, GEMM_SMEM);
        cudaFuncSetAttribute(attn_kernel,
                             cudaFuncAttributeMaxDynamicSharedMemorySize, ATTN_SMEM);
        attr_set = true;
    }

    // ---- operand prep: weight transpose+split (x4), x split ----
    dim3 wt(32, 8);
    wtrans_kernel<<<dim3(32, 32), wt>>>(Wq, wqh, wql);
    wtrans_kernel<<<dim3(32, 32), wt>>>(Wk, wkh, wkl);
    wtrans_kernel<<<dim3(32, 32), wt>>>(Wv, wvh, wvl);
    wtrans_kernel<<<dim3(32, 32), wt>>>(Wp, wph, wpl);
    cvt_split_kernel<<<NTOK * DD / 1024, 256>>>(x, xhi, xlo);

    // ---- fused QKV projections (tensor cores), head-major out ----
    // Q pre-scaled by 1/sqrt(HD) * log2(e) for base-2 softmax.
    const float qscale = 0.125f * LOG2E;
    dim3 gb(DD / 128, NTOK / 128, 3);   // (8, 32, 3)
    gemm_tc_kernel<<<gb, 512, GEMM_SMEM>>>(
        xhi, xlo, wqh, wql, wkh, wkl, wvh, wvl,
        bq, bk, bv, q_ptr, k_ptr, v_ptr, qscale, 1.0f, 1.0f, 1);

    // ---- attention (FFMA2 fp32) ----
    dim3 ga(SS / 128, BB * HH);         // (16, 32)
    attn_kernel<<<ga, 256, ATTN_SMEM>>>();

    // ---- output projection (tensor cores), token-major ----
    cvt_split_kernel<<<NTOK * DD / 1024, 256>>>(attn_ptr, ahi, alo);
    dim3 gp(DD / 128, NTOK / 128, 1);
    gemm_tc_kernel<<<gp, 512, GEMM_SMEM>>>(
        ahi, alo, wph, wpl, wph, wpl, wph, wpl,
        bp, bp, bp, proj_ptr, proj_ptr, proj_ptr, 1.0f, 1.0f, 1.0f, 0);

    // ---- residual + LayerNorm ----
    ln_kernel<<<NTOK, 256>>>(x, gamma, beta, out);
}

// round 8
// speedup vs baseline: 9.7592x; 1.8751x over previous
#include <cuda_runtime.h>
#include <cuda_bf16.h>
#include <cstdint>

// Problem constants
#define BB 2
#define SS 2048
#define DD 1024
#define HH 16
#define HD 64
#define NTOK (BB*SS)          // 4096
#define EPS 1e-5f
#define LOG2E 1.44269504088896340736f

// ---------------- misc helpers --------------------------------------------
__device__ __forceinline__ float fexp2(float x) {
    float y; asm("ex2.approx.ftz.f32 %0, %1;" : "=f"(y) : "f"(x)); return y;
}
__device__ __forceinline__ uint32_t smem_u32(const void* p) {
    uint32_t a;
    asm("{ .reg .u64 t; cvta.to.shared.u64 t, %1; cvt.u32.u64 %0, t; }" : "=r"(a) : "l"(p));
    return a;
}
// pack (lo, hi) floats -> bf16x2 (lo in low half)
__device__ __forceinline__ uint32_t pkbf(float lo, float hi) {
    uint32_t r; asm("cvt.rn.bf16x2.f32 %0, %1, %2;" : "=r"(r) : "f"(hi), "f"(lo)); return r;
}

// ---------------- mma.sync / ldmatrix (base-ISA tensor cores) --------------
__device__ __forceinline__ void ldm4(uint32_t* r, uint32_t addr) {
    asm volatile("ldmatrix.sync.aligned.m8n8.x4.shared.b16 {%0,%1,%2,%3}, [%4];"
        : "=r"(r[0]), "=r"(r[1]), "=r"(r[2]), "=r"(r[3]) : "r"(addr));
}
__device__ __forceinline__ void ldm4t(uint32_t* r, uint32_t addr) {
    asm volatile("ldmatrix.sync.aligned.m8n8.x4.trans.shared.b16 {%0,%1,%2,%3}, [%4];"
        : "=r"(r[0]), "=r"(r[1]), "=r"(r[2]), "=r"(r[3]) : "r"(addr));
}
__device__ __forceinline__ void mma16816(float* c, const uint32_t* a, const uint32_t* b) {
    asm volatile("mma.sync.aligned.m16n8k16.row.col.f32.bf16.bf16.f32 "
        "{%0,%1,%2,%3}, {%4,%5,%6,%7}, {%8,%9}, {%0,%1,%2,%3};"
        : "+f"(c[0]), "+f"(c[1]), "+f"(c[2]), "+f"(c[3])
        : "r"(a[0]), "r"(a[1]), "r"(a[2]), "r"(a[3]), "r"(b[0]), "r"(b[1]));
}

// ---------------- device scratch (allocation-free rule: device globals) ----
// Q/K/V head-major [B,H,S,HD] bf16 hi/lo (Q pre-scaled by 0.125*log2e)
__device__ __align__(16) __nv_bfloat16 g_qhi[(size_t)BB*HH*SS*HD];
__device__ __align__(16) __nv_bfloat16 g_qlo[(size_t)BB*HH*SS*HD];
__device__ __align__(16) __nv_bfloat16 g_khi[(size_t)BB*HH*SS*HD];
__device__ __align__(16) __nv_bfloat16 g_klo[(size_t)BB*HH*SS*HD];
__device__ __align__(16) __nv_bfloat16 g_vhi[(size_t)BB*HH*SS*HD];
__device__ __align__(16) __nv_bfloat16 g_vlo[(size_t)BB*HH*SS*HD];
// attention output token-major bf16 hi/lo (feeds proj GEMM)
__device__ __align__(16) __nv_bfloat16 g_ahi[(size_t)NTOK*DD];
__device__ __align__(16) __nv_bfloat16 g_alo[(size_t)NTOK*DD];
// x split
__device__ __align__(16) __nv_bfloat16 g_xhi[(size_t)NTOK*DD];
__device__ __align__(16) __nv_bfloat16 g_xlo[(size_t)NTOK*DD];
// proj output fp32 token-major
__device__ float g_proj[(size_t)NTOK*DD];
// transposed weights WT[n][k], hi/lo
__device__ __align__(16) __nv_bfloat16 g_wq_hi[(size_t)DD*DD];
__device__ __align__(16) __nv_bfloat16 g_wq_lo[(size_t)DD*DD];
__device__ __align__(16) __nv_bfloat16 g_wk_hi[(size_t)DD*DD];
__device__ __align__(16) __nv_bfloat16 g_wk_lo[(size_t)DD*DD];
__device__ __align__(16) __nv_bfloat16 g_wv_hi[(size_t)DD*DD];
__device__ __align__(16) __nv_bfloat16 g_wv_lo[(size_t)DD*DD];
__device__ __align__(16) __nv_bfloat16 g_wp_hi[(size_t)DD*DD];
__device__ __align__(16) __nv_bfloat16 g_wp_lo[(size_t)DD*DD];

// ---------------------------------------------------------------------------
// Elementwise fp32 -> (bf16 hi, bf16 lo) split.
// ---------------------------------------------------------------------------
__global__ void __launch_bounds__(256) cvt_split_kernel(
    const float* __restrict__ in, __nv_bfloat16* __restrict__ hi,
    __nv_bfloat16* __restrict__ lo)
{
    const int i = blockIdx.x * 256 + threadIdx.x;
    float4 v = ((const float4*)in)[i];
    __nv_bfloat16 h0 = __float2bfloat16(v.x);
    __nv_bfloat16 h1 = __float2bfloat16(v.y);
    __nv_bfloat16 h2 = __float2bfloat16(v.z);
    __nv_bfloat16 h3 = __float2bfloat16(v.w);
    __nv_bfloat16 l0 = __float2bfloat16(v.x - __bfloat162float(h0));
    __nv_bfloat16 l1 = __float2bfloat16(v.y - __bfloat162float(h1));
    __nv_bfloat16 l2 = __float2bfloat16(v.z - __bfloat162float(h2));
    __nv_bfloat16 l3 = __float2bfloat16(v.w - __bfloat162float(h3));
    __nv_bfloat162* hp = (__nv_bfloat162*)hi;
    __nv_bfloat162* lp = (__nv_bfloat162*)lo;
    hp[2*i]   = __nv_bfloat162(h0, h1);
    hp[2*i+1] = __nv_bfloat162(h2, h3);
    lp[2*i]   = __nv_bfloat162(l0, l1);
    lp[2*i+1] = __nv_bfloat162(l2, l3);
}

// ---------------------------------------------------------------------------
// W fp32 [k][n] -> WT hi/lo bf16 [n][k], fused 4 weights via blockIdx.z.
// ---------------------------------------------------------------------------
__global__ void __launch_bounds__(256) wtrans_kernel(
    const float* __restrict__ W0, const float* __restrict__ W1,
    const float* __restrict__ W2, const float* __restrict__ W3,
    __nv_bfloat16* __restrict__ T0h, __nv_bfloat16* __restrict__ T0l,
    __nv_bfloat16* __restrict__ T1h, __nv_bfloat16* __restrict__ T1l,
    __nv_bfloat16* __restrict__ T2h, __nv_bfloat16* __restrict__ T2l,
    __nv_bfloat16* __restrict__ T3h, __nv_bfloat16* __restrict__ T3l)
{
    __shared__ float tile[32][33];
    const int z = blockIdx.z;
    const float* W = (z == 0) ? W0 : (z == 1) ? W1 : (z == 2) ? W2 : W3;
    __nv_bfloat16* Thi = (z == 0) ? T0h : (z == 1) ? T1h : (z == 2) ? T2h : T3h;
    __nv_bfloat16* Tlo = (z == 0) ? T0l : (z == 1) ? T1l : (z == 2) ? T2l : T3l;

    const int tx = threadIdx.x, ty = threadIdx.y;
    const int n0 = blockIdx.x * 32, k0 = blockIdx.y * 32;
#pragma unroll
    for (int r = ty; r < 32; r += 8)
        tile[r][tx] = W[(size_t)(k0 + r) * DD + n0 + tx];
    __syncthreads();
#pragma unroll
    for (int r = ty; r < 32; r += 8) {
        const int n = n0 + r, k = k0 + tx;
        const float v = tile[tx][r];
        __nv_bfloat16 h = __float2bfloat16(v);
        __nv_bfloat16 l = __float2bfloat16(v - __bfloat162float(h));
        Thi[(size_t)n * DD + k] = h;
        Tlo[(size_t)n * DD + k] = l;
    }
}

// ---------------------------------------------------------------------------
// Tensor-core GEMM (mma.sync, split-bf16, fp32 accumulate):
// C[4096,1024] = A @ W + bias (*scale).
// mode head_major=1: write bf16 hi/lo head-major [B,H,S,HD] (QKV).
// mode head_major=0: write fp32 token-major (proj).
// CTA 128x128, 512 thr (16 warps 4x4), warp tile 32x32, 3-MMA split.
// ---------------------------------------------------------------------------
#define KCH 128
#define LDT 136
#define TILE_HALFS (128 * LDT)
#define TILE_BYTES (TILE_HALFS * 2)
#define GEMM_SMEM (4 * TILE_BYTES)      // 139264

__global__ void __launch_bounds__(512) gemm_tc_kernel(
    const __nv_bfloat16* __restrict__ Ahi, const __nv_bfloat16* __restrict__ Alo,
    const __nv_bfloat16* __restrict__ W0h, const __nv_bfloat16* __restrict__ W0l,
    const __nv_bfloat16* __restrict__ W1h, const __nv_bfloat16* __restrict__ W1l,
    const __nv_bfloat16* __restrict__ W2h, const __nv_bfloat16* __restrict__ W2l,
    const float* __restrict__ b0, const float* __restrict__ b1, const float* __restrict__ b2,
    __nv_bfloat16* __restrict__ C0h, __nv_bfloat16* __restrict__ C0l,
    __nv_bfloat16* __restrict__ C1h, __nv_bfloat16* __restrict__ C1l,
    __nv_bfloat16* __restrict__ C2h, __nv_bfloat16* __restrict__ C2l,
    float* __restrict__ Cf,
    float s0, float s1, float s2, int head_major)
{
    extern __shared__ __nv_bfloat16 smem[];
    __nv_bfloat16* sAhi = smem;
    __nv_bfloat16* sAlo = smem + TILE_HALFS;
    __nv_bfloat16* sBhi = smem + 2 * TILE_HALFS;
    __nv_bfloat16* sBlo = smem + 3 * TILE_HALFS;

    const int z = blockIdx.z;
    const __nv_bfloat16* Bhi = (z == 0) ? W0h : (z == 1) ? W1h : W2h;
    const __nv_bfloat16* Blo = (z == 0) ? W0l : (z == 1) ? W1l : W2l;
    const float* bias = (z == 0) ? b0 : (z == 1) ? b1 : b2;
    __nv_bfloat16* Chi = (z == 0) ? C0h : (z == 1) ? C1h : C2h;
    __nv_bfloat16* Clo = (z == 0) ? C0l : (z == 1) ? C1l : C2l;
    const float scale = (z == 0) ? s0 : (z == 1) ? s1 : s2;

    const int tid  = threadIdx.x;
    const int wid  = tid >> 5;
    const int lane = tid & 31;
    const int wm   = wid >> 2;
    const int wn   = wid & 3;
    const int brow = blockIdx.y * 128;
    const int bcol = blockIdx.x * 128;

    float c[2][4][4];
#pragma unroll
    for (int i = 0; i < 2; i++)
#pragma unroll
        for (int j = 0; j < 4; j++)
#pragma unroll
            for (int q = 0; q < 4; q++) c[i][j][q] = 0.f;

    const uint32_t aRow = (lane & 7) + ((lane >> 3) & 1) * 8;
    const uint32_t aKof = (lane >> 4) * 8;
    const uint32_t bRow = (lane & 7) + (lane >> 4) * 8;
    const uint32_t bKof = ((lane >> 3) & 1) * 8;

    const uint32_t sbase = smem_u32(smem);
    const uint32_t aHiB = sbase + ((32 * wm + aRow) * LDT + aKof) * 2;
    const uint32_t aLoB = aHiB + TILE_BYTES;
    const uint32_t bHiB = sbase + 2u * TILE_BYTES + ((32 * wn + bRow) * LDT + bKof) * 2;
    const uint32_t bLoB = bHiB + TILE_BYTES;

    for (int kc = 0; kc < DD; kc += KCH) {
        __syncthreads();
#pragma unroll
        for (int rep = 0; rep < 4; rep++) {
            const int idx = tid + rep * 512;
            const int row = idx >> 4;
            const int c8  = idx & 15;
            const size_t goff = (size_t)row * DD + kc + c8 * 8;
            const uint32_t soff = row * LDT + c8 * 8;
            *(uint4*)(sAhi + soff) = *(const uint4*)(Ahi + (size_t)brow * DD + goff);
            *(uint4*)(sAlo + soff) = *(const uint4*)(Alo + (size_t)brow * DD + goff);
            *(uint4*)(sBhi + soff) = *(const uint4*)(Bhi + (size_t)bcol * DD + goff);
            *(uint4*)(sBlo + soff) = *(const uint4*)(Blo + (size_t)bcol * DD + goff);
        }
        __syncthreads();

#pragma unroll
        for (int s = 0; s < 8; s++) {
            uint32_t ah[2][4], al[2][4], bh[4][2], bl[4][2];
            const uint32_t sb = s * 32;
            ldm4(ah[0], aHiB + sb);
            ldm4(ah[1], aHiB + 16 * LDT * 2 + sb);
            ldm4(al[0], aLoB + sb);
            ldm4(al[1], aLoB + 16 * LDT * 2 + sb);
            ldm4(&bh[0][0], bHiB + sb);
            ldm4(&bh[2][0], bHiB + 16 * LDT * 2 + sb);
            ldm4(&bl[0][0], bLoB + sb);
            ldm4(&bl[2][0], bLoB + 16 * LDT * 2 + sb);
#pragma unroll
            for (int i = 0; i < 2; i++)
#pragma unroll
                for (int j = 0; j < 4; j++) {
                    mma16816(c[i][j], ah[i], bh[j]);
                    mma16816(c[i][j], ah[i], bl[j]);
                    mma16816(c[i][j], al[i], bh[j]);
                }
        }
    }

    const int rbase = brow + 32 * wm + (lane >> 2);
    const int cbase = bcol + 32 * wn + 2 * (lane & 3);
#pragma unroll
    for (int i = 0; i < 2; i++) {
#pragma unroll
        for (int j = 0; j < 4; j++) {
            const int col = cbase + 8 * j;
            const float2 bb = *(const float2*)&bias[col];
#pragma unroll
            for (int half = 0; half < 2; half++) {
                const int row = rbase + 16 * i + 8 * half;
                float ox = (c[i][j][2 * half + 0] + bb.x) * scale;
                float oy = (c[i][j][2 * half + 1] + bb.y) * scale;
                const int bidx = row >> 11, srow = row & 2047;
                if (head_major) {
                    const int h = col >> 6, hd = col & 63;
                    const size_t idx = (((size_t)bidx * HH + h) * SS + srow) * HD + hd;
                    __nv_bfloat16 h0 = __float2bfloat16(ox);
                    __nv_bfloat16 h1 = __float2bfloat16(oy);
                    *(__nv_bfloat162*)(Chi + idx) = __nv_bfloat162(h0, h1);
                    *(__nv_bfloat162*)(Clo + idx) = __nv_bfloat162(
                        __float2bfloat16(ox - __bfloat162float(h0)),
                        __float2bfloat16(oy - __bfloat162float(h1)));
                } else {
                    float2 o; o.x = ox; o.y = oy;
                    *(float2*)&Cf[(size_t)row * DD + col] = o;
                }
            }
        }
    }
}

// ---------------------------------------------------------------------------
// Tensor-core flash attention (mma.sync, split-bf16, FA2 register-resident P).
// Grid (16, 32): (q-tile of 128, b*h). 256 threads = 8 warps, warp = 16 q rows.
// Key tile 64. Per tile: S = QK^T (3 MMAs/frag), base-2 online softmax on
// fragments, P split hi/lo in registers, O += P@V (3 MMAs/frag, V via
// ldmatrix.trans). Output written bf16 hi/lo token-major for the proj GEMM.
// ---------------------------------------------------------------------------
#define ALD 72   // halfs per smem row (144B stride -> conflict-free ldmatrix)
#define ATTN_SMEM ((2*128 + 4*64) * ALD * 2)    // 73728 B

__global__ void __launch_bounds__(256, 2) attn_tc_kernel()
{
    extern __shared__ __nv_bfloat16 smh[];
    __nv_bfloat16* sQhi = smh;
    __nv_bfloat16* sQlo = smh + 128 * ALD;
    __nv_bfloat16* sKhi = smh + 2 * 128 * ALD;
    __nv_bfloat16* sKlo = sKhi + 64 * ALD;
    __nv_bfloat16* sVhi = sKlo + 64 * ALD;
    __nv_bfloat16* sVlo = sVhi + 64 * ALD;

    const int bh = blockIdx.y;
    const int qt = blockIdx.x;
    const int tid = threadIdx.x;
    const int wid = tid >> 5;
    const int lane = tid & 31;

    // ---- load Q tile (128 x 64 halfs, hi+lo) ----
    const __nv_bfloat16* qhb = g_qhi + ((size_t)bh * SS + qt * 128) * HD;
    const __nv_bfloat16* qlb = g_qlo + ((size_t)bh * SS + qt * 128) * HD;
#pragma unroll
    for (int rep = 0; rep < 4; rep++) {
        const int i = tid + rep * 256;        // 0..1023
        const int row = i >> 3, c8 = i & 7;
        const uint32_t soff = row * ALD + c8 * 8;
        *(uint4*)(sQhi + soff) = *(const uint4*)(qhb + (size_t)row * HD + c8 * 8);
        *(uint4*)(sQlo + soff) = *(const uint4*)(qlb + (size_t)row * HD + c8 * 8);
    }

    // fragment base addresses (bytes)
    const uint32_t sb = smem_u32(smh);
    const uint32_t aQhi = sb + ((16 * wid + (lane & 15)) * ALD + ((lane >> 4) << 3)) * 2;
    const uint32_t aQlo = aQhi + 128 * ALD * 2;
    const uint32_t kRowOff = ((lane & 7) + ((lane >> 4) << 3)) * ALD + (((lane >> 3) & 1) << 3);
    const uint32_t aKhi = sb + (2 * 128 * ALD + kRowOff) * 2;
    const uint32_t aKlo = aKhi + 64 * ALD * 2;
    const uint32_t vRowOff = (lane & 15) * ALD + ((lane >> 4) << 3);
    const uint32_t aVhi = sb + (2 * 128 * ALD + 2 * 64 * ALD + vRowOff) * 2;
    const uint32_t aVlo = aVhi + 64 * ALD * 2;

    float O[8][4];
#pragma unroll
    for (int j = 0; j < 8; j++)
#pragma unroll
        for (int q = 0; q < 4; q++) O[j][q] = 0.f;
    float m0 = -1e30f, m1 = -1e30f, l0 = 0.f, l1 = 0.f;

    const __nv_bfloat16* khb = g_khi + (size_t)bh * SS * HD;
    const __nv_bfloat16* klb = g_klo + (size_t)bh * SS * HD;
    const __nv_bfloat16* vhb = g_vhi + (size_t)bh * SS * HD;
    const __nv_bfloat16* vlb = g_vlo + (size_t)bh * SS * HD;

    for (int kt0 = 0; kt0 < SS; kt0 += 64) {
        __syncthreads();
        // stage K/V tiles (64 x 64 halfs each, hi+lo)
#pragma unroll
        for (int rep = 0; rep < 2; rep++) {
            const int i = tid + rep * 256;    // 0..511
            const int row = i >> 3, c8 = i & 7;
            const size_t goff = (size_t)(kt0 + row) * HD + c8 * 8;
            const uint32_t soff = row * ALD + c8 * 8;
            *(uint4*)(sKhi + soff) = *(const uint4*)(khb + goff);
            *(uint4*)(sKlo + soff) = *(const uint4*)(klb + goff);
            *(uint4*)(sVhi + soff) = *(const uint4*)(vhb + goff);
            *(uint4*)(sVlo + soff) = *(const uint4*)(vlb + goff);
        }
        __syncthreads();

        // ---- S = Q K^T (per warp: 16 rows x 64 keys), split 3-MMA ----
        float S[8][4];
#pragma unroll
        for (int j = 0; j < 8; j++)
#pragma unroll
            for (int q = 0; q < 4; q++) S[j][q] = 0.f;

#pragma unroll
        for (int ks = 0; ks < 4; ks++) {
            uint32_t ah[4], al[4];
            ldm4(ah, aQhi + ks * 32);
            ldm4(al, aQlo + ks * 32);
#pragma unroll
            for (int g = 0; g < 4; g++) {
                uint32_t bh16[4], bl16[4];
                const uint32_t off = (g * 16 * ALD + ks * 16) * 2;
                ldm4(bh16, aKhi + off);
                ldm4(bl16, aKlo + off);
                mma16816(S[2*g],   ah, bh16 + 0);
                mma16816(S[2*g],   ah, bl16 + 0);
                mma16816(S[2*g],   al, bh16 + 0);
                mma16816(S[2*g+1], ah, bh16 + 2);
                mma16816(S[2*g+1], ah, bl16 + 2);
                mma16816(S[2*g+1], al, bh16 + 2);
            }
        }

        // ---- online softmax on fragments (rows lane>>2 and +8), base-2 ----
        float t0 = -1e30f, t1 = -1e30f;
#pragma unroll
        for (int j = 0; j < 8; j++) {
            t0 = fmaxf(t0, fmaxf(S[j][0], S[j][1]));
            t1 = fmaxf(t1, fmaxf(S[j][2], S[j][3]));
        }
        t0 = fmaxf(t0, __shfl_xor_sync(0xffffffffu, t0, 1));
        t0 = fmaxf(t0, __shfl_xor_sync(0xffffffffu, t0, 2));
        t1 = fmaxf(t1, __shfl_xor_sync(0xffffffffu, t1, 1));
        t1 = fmaxf(t1, __shfl_xor_sync(0xffffffffu, t1, 2));
        const float mn0 = fmaxf(m0, t0), mn1 = fmaxf(m1, t1);
        const float al0 = fexp2(m0 - mn0), al1 = fexp2(m1 - mn1);
        m0 = mn0; m1 = mn1;

        float ps0 = 0.f, ps1 = 0.f;
#pragma unroll
        for (int j = 0; j < 8; j++) {
            S[j][0] = fexp2(S[j][0] - mn0);
            S[j][1] = fexp2(S[j][1] - mn0);
            S[j][2] = fexp2(S[j][2] - mn1);
            S[j][3] = fexp2(S[j][3] - mn1);
            ps0 += S[j][0] + S[j][1];
            ps1 += S[j][2] + S[j][3];
        }
        ps0 += __shfl_xor_sync(0xffffffffu, ps0, 1);
        ps0 += __shfl_xor_sync(0xffffffffu, ps0, 2);
        ps1 += __shfl_xor_sync(0xffffffffu, ps1, 1);
        ps1 += __shfl_xor_sync(0xffffffffu, ps1, 2);
        l0 = l0 * al0 + ps0;
        l1 = l1 * al1 + ps1;

#pragma unroll
        for (int j = 0; j < 8; j++) {
            O[j][0] *= al0; O[j][1] *= al0;
            O[j][2] *= al1; O[j][3] *= al1;
        }

        // ---- O += P V, P split hi/lo in registers ----
#pragma unroll
        for (int ks = 0; ks < 4; ks++) {
            uint32_t phi[4], plo[4];
#pragma unroll
            for (int u = 0; u < 2; u++) {
                const float* f = S[2 * ks + u];
                uint32_t h01 = pkbf(f[0], f[1]);
                uint32_t h23 = pkbf(f[2], f[3]);
                phi[2 * u + 0] = h01;
                phi[2 * u + 1] = h23;
                const float hx0 = __uint_as_float(h01 << 16);
                const float hy0 = __uint_as_float(h01 & 0xffff0000u);
                const float hx1 = __uint_as_float(h23 << 16);
                const float hy1 = __uint_as_float(h23 & 0xffff0000u);
                plo[2 * u + 0] = pkbf(f[0] - hx0, f[1] - hy0);
                plo[2 * u + 1] = pkbf(f[2] - hx1, f[3] - hy1);
            }
#pragma unroll
            for (int g = 0; g < 4; g++) {
                uint32_t vh[4], vl[4];
                const uint32_t off = (ks * 16 * ALD + g * 16) * 2;
                ldm4t(vh, aVhi + off);
                ldm4t(vl, aVlo + off);
                mma16816(O[2*g],   phi, vh + 0);
                mma16816(O[2*g],   phi, vl + 0);
                mma16816(O[2*g],   plo, vh + 0);
                mma16816(O[2*g+1], phi, vh + 2);
                mma16816(O[2*g+1], phi, vl + 2);
                mma16816(O[2*g+1], plo, vh + 2);
            }
        }
    }

    // ---- normalize + write bf16 hi/lo token-major (merge heads) ----
    const float inv0 = 1.f / l0, inv1 = 1.f / l1;
    const int b = bh >> 4, h = bh & 15;
    const int r0 = qt * 128 + 16 * wid + (lane >> 2);
    const size_t tok0 = (size_t)b * SS + r0;
    const size_t tok1 = tok0 + 8;
#pragma unroll
    for (int j = 0; j < 8; j++) {
        const int col = h * HD + 8 * j + 2 * (lane & 3);
        float x0 = O[j][0] * inv0, y0 = O[j][1] * inv0;
        float x1 = O[j][2] * inv1, y1 = O[j][3] * inv1;
        __nv_bfloat16 h0 = __float2bfloat16(x0), h1 = __float2bfloat16(y0);
        __nv_bfloat16 h2 = __float2bfloat16(x1), h3 = __float2bfloat16(y1);
        *(__nv_bfloat162*)(g_ahi + tok0 * DD + col) = __nv_bfloat162(h0, h1);
        *(__nv_bfloat162*)(g_alo + tok0 * DD + col) = __nv_bfloat162(
            __float2bfloat16(x0 - __bfloat162float(h0)),
            __float2bfloat16(y0 - __bfloat162float(h1)));
        *(__nv_bfloat162*)(g_ahi + tok1 * DD + col) = __nv_bfloat162(h2, h3);
        *(__nv_bfloat162*)(g_alo + tok1 * DD + col) = __nv_bfloat162(
            __float2bfloat16(x1 - __bfloat162float(h2)),
            __float2bfloat16(y1 - __bfloat162float(h3)));
    }
}

// ---------------------------------------------------------------------------
// Residual + LayerNorm: 1 block per token row.
// ---------------------------------------------------------------------------
__global__ void __launch_bounds__(256) ln_kernel(
    const float* __restrict__ x, const float* __restrict__ gamma,
    const float* __restrict__ beta, float* __restrict__ out)
{
    __shared__ float ssum[8], ssq[8];
    const int row = blockIdx.x;
    const int t = threadIdx.x;

    float4 xv = ((const float4*)(x      + (size_t)row * DD))[t];
    float4 pv = ((const float4*)(g_proj + (size_t)row * DD))[t];
    float4 y;
    y.x = xv.x + pv.x; y.y = xv.y + pv.y; y.z = xv.z + pv.z; y.w = xv.w + pv.w;

    float s  = y.x + y.y + y.z + y.w;
    float sq = y.x * y.x + y.y * y.y + y.z * y.z + y.w * y.w;
#pragma unroll
    for (int off = 16; off > 0; off >>= 1) {
        s  += __shfl_xor_sync(0xffffffffu, s,  off);
        sq += __shfl_xor_sync(0xffffffffu, sq, off);
    }
    const int warp = t >> 5;
    if ((t & 31) == 0) { ssum[warp] = s; ssq[warp] = sq; }
    __syncthreads();
    float tot = 0.f, totq = 0.f;
#pragma unroll
    for (int i = 0; i < 8; i++) { tot += ssum[i]; totq += ssq[i]; }

    const float mu   = tot * (1.f / DD);
    const float var  = totq * (1.f / DD) - mu * mu;
    const float rstd = rsqrtf(var + EPS);

    float4 g = ((const float4*)gamma)[t];
    float4 b = ((const float4*)beta)[t];
    float4 o;
    o.x = (y.x - mu) * rstd * g.x + b.x;
    o.y = (y.y - mu) * rstd * g.y + b.y;
    o.z = (y.z - mu) * rstd * g.z + b.z;
    o.w = (y.w - mu) * rstd * g.w + b.w;
    ((float4*)(out + (size_t)row * DD))[t] = o;
}

// ---------------------------------------------------------------------------
extern "C" void kernel_launch(void* const* d_in, const int* in_sizes, int n_in,
                              void* d_out, int out_size)
{
    const float* x     = (const float*)d_in[0];
    const float* Wq    = (const float*)d_in[1];
    const float* bq    = (const float*)d_in[2];
    const float* Wk    = (const float*)d_in[3];
    const float* bk    = (const float*)d_in[4];
    const float* Wv    = (const float*)d_in[5];
    const float* bv    = (const float*)d_in[6];
    const float* Wp    = (const float*)d_in[7];
    const float* bp    = (const float*)d_in[8];
    const float* gamma = (const float*)d_in[9];
    const float* beta  = (const float*)d_in[10];
    float* out = (float*)d_out;

    __nv_bfloat16 *qh, *ql, *kh, *kl, *vh, *vl, *ah, *al, *xh, *xl;
    __nv_bfloat16 *wqh, *wql, *wkh, *wkl, *wvh, *wvl, *wph, *wpl;
    float* proj_ptr;
    cudaGetSymbolAddress((void**)&qh, g_qhi);
    cudaGetSymbolAddress((void**)&ql, g_qlo);
    cudaGetSymbolAddress((void**)&kh, g_khi);
    cudaGetSymbolAddress((void**)&kl, g_klo);
    cudaGetSymbolAddress((void**)&vh, g_vhi);
    cudaGetSymbolAddress((void**)&vl, g_vlo);
    cudaGetSymbolAddress((void**)&ah, g_ahi);
    cudaGetSymbolAddress((void**)&al, g_alo);
    cudaGetSymbolAddress((void**)&xh, g_xhi);
    cudaGetSymbolAddress((void**)&xl, g_xlo);
    cudaGetSymbolAddress((void**)&proj_ptr, g_proj);
    cudaGetSymbolAddress((void**)&wqh, g_wq_hi);
    cudaGetSymbolAddress((void**)&wql, g_wq_lo);
    cudaGetSymbolAddress((void**)&wkh, g_wk_hi);
    cudaGetSymbolAddress((void**)&wkl, g_wk_lo);
    cudaGetSymbolAddress((void**)&wvh, g_wv_hi);
    cudaGetSymbolAddress((void**)&wvl, g_wv_lo);
    cudaGetSymbolAddress((void**)&wph, g_wp_hi);
    cudaGetSymbolAddress((void**)&wpl, g_wp_lo);

    static bool attr_set = false;
    if (!attr_set) {
        cudaFuncSetAttribute(gemm_tc_kernel,
                             cudaFuncAttributeMaxDynamicSharedMemorySize, GEMM_SMEM);
        cudaFuncSetAttribute(attn_tc_kernel,
                             cudaFuncAttributeMaxDynamicSharedMemorySize, ATTN_SMEM);
        attr_set = true;
    }

    // ---- operand prep: fused weight transpose+split, x split ----
    wtrans_kernel<<<dim3(32, 32, 4), dim3(32, 8)>>>(
        Wq, Wk, Wv, Wp, wqh, wql, wkh, wkl, wvh, wvl, wph, wpl);
    cvt_split_kernel<<<NTOK * DD / 1024, 256>>>(x, xh, xl);

    // ---- fused QKV projections -> bf16 hi/lo head-major ----
    // Q pre-scaled by 1/sqrt(HD) * log2(e) for base-2 softmax.
    const float qscale = 0.125f * LOG2E;
    dim3 gb(DD / 128, NTOK / 128, 3);
    gemm_tc_kernel<<<gb, 512, GEMM_SMEM>>>(
        xh, xl, wqh, wql, wkh, wkl, wvh, wvl,
        bq, bk, bv,
        qh, ql, kh, kl, vh, vl, nullptr,
        qscale, 1.0f, 1.0f, 1);

    // ---- tensor-core flash attention -> bf16 hi/lo token-major ----
    dim3 ga(SS / 128, BB * HH);
    attn_tc_kernel<<<ga, 256, ATTN_SMEM>>>();

    // ---- output projection -> fp32 token-major ----
    dim3 gp(DD / 128, NTOK / 128, 1);
    gemm_tc_kernel<<<gp, 512, GEMM_SMEM>>>(
        ah, al, wph, wpl, wph, wpl, wph, wpl,
        bp, bp, bp,
        nullptr, nullptr, nullptr, nullptr, nullptr, nullptr, proj_ptr,
        1.0f, 1.0f, 1.0f, 0);

    // ---- residual + LayerNorm ----
    ln_kernel<<<NTOK, 256>>>(x, gamma, beta, out);
}